// round 14
// baseline (speedup 1.0000x reference)
#include <cuda_runtime.h>
#include <cuda_bf16.h>
#include <math.h>
#include <stdint.h>

#define BB 2
#define LL 1024
#define DM 768
#define NLAYER 2
#define DI 1536
#define NS 16
#define DTR 48
#define XD 80           // DTR + 2*NS
#define XDP 128         // padded x_dbl width
#define SS 4            // augmented batch: [fwd b0, fwd b1, bwd b0, bwd b1]
#define M4 (SS*LL)      // 4096 rows (augmented)
#define M2 (2*LL)       // 2048 rows (fwd only, in_proj GEMM)

// ---------------- scratch (static __device__, no allocation) ----------------
__device__ __align__(128) float g_h[BB*LL*DM];
__device__ __align__(128) float g_res[BB*LL*DM];
__device__ __align__(128) float g_resA[SS*LL*DM];
__device__ __align__(128) float g_xz[M2*2*DI];          // fwd only
__device__ __align__(128) float g_xc[SS*LL*DI];
__device__ __align__(128) float g_xdbl[M4*XDP];
__device__ __align__(128) float g_delta[SS*LL*DI];
__device__ __align__(128) float g_bo[SS*LL*DM];
__device__ __align__(128) float g_fin[BB*LL*DM];

// split-bf16 activation/weight planes: [hi plane][lo plane], row-major
__device__ __align__(128) __nv_bfloat16 g_pa768 [2*M4*DM];
__device__ __align__(128) __nv_bfloat16 g_pa1536[2*M4*DI];
__device__ __align__(128) __nv_bfloat16 g_pw_in [NLAYER*2*(2*DI)*DM];
__device__ __align__(128) __nv_bfloat16 g_pw_fc1[NLAYER*2*(2*DI)*DM];
__device__ __align__(128) __nv_bfloat16 g_pw_out[NLAYER*2*DM*DI];
__device__ __align__(128) __nv_bfloat16 g_pw_fc2[NLAYER*2*DM*DI];
__device__ __align__(128) __nv_bfloat16 g_pw_xp [NLAYER*2*XDP*DI];

__device__ __forceinline__ float siluf(float x){ return x/(1.f+__expf(-x)); }

__device__ __forceinline__ void split_bf16(float v, __nv_bfloat16& h, __nv_bfloat16& l){
  h = __float2bfloat16(v);
  l = __float2bfloat16(v - __bfloat162float(h));
}

// ---------------- elementwise kernels ----------------
__global__ void embed_kernel(const int* __restrict__ ids, const float* __restrict__ emb,
                             float* __restrict__ out){
  int i = blockIdx.x*blockDim.x+threadIdx.x;
  if(i>=BB*LL*DM) return;
  int d=i%DM; int t=i/DM;
  out[i] = emb[(size_t)ids[t]*DM + d];
}

// Fused: v = h (+res); resA[fwd]=resA[bwd-mirror]=v; LN(v) -> split-bf16 planes (FWD rows only).
__global__ void aug_ln_pack_kernel(const float* __restrict__ h, const float* __restrict__ res,
                                   float* __restrict__ resA, __nv_bfloat16* __restrict__ pk,
                                   const float* __restrict__ w, const float* __restrict__ bias,
                                   int use_res){
  int r = blockIdx.x;              // 0 .. BB*LL-1
  int b = r / LL, l = r % LL;
  size_t fbase = (size_t)(b*LL + l)*DM;
  size_t rbase = (size_t)((2+b)*LL + (LL-1-l))*DM;
  float v[3]; float s=0.f,s2=0.f;
  #pragma unroll
  for(int j=0;j<3;j++){
    int idx = threadIdx.x + j*256;
    float t = h[fbase+idx];
    if(use_res) t += res[fbase+idx];
    v[j]=t; s+=t; s2+=t*t;
    resA[fbase+idx]=t; resA[rbase+idx]=t;
  }
  #pragma unroll
  for(int o=16;o>0;o>>=1){ s+=__shfl_xor_sync(0xffffffffu,s,o); s2+=__shfl_xor_sync(0xffffffffu,s2,o); }
  __shared__ float sh[2][8];
  int wid=threadIdx.x>>5, lane=threadIdx.x&31;
  if(lane==0){ sh[0][wid]=s; sh[1][wid]=s2; }
  __syncthreads();
  if(threadIdx.x<32){
    float a = lane<8? sh[0][lane]:0.f;
    float b2= lane<8? sh[1][lane]:0.f;
    #pragma unroll
    for(int o=4;o>0;o>>=1){ a+=__shfl_xor_sync(0xffffffffu,a,o); b2+=__shfl_xor_sync(0xffffffffu,b2,o); }
    if(lane==0){ sh[0][0]=a; sh[1][0]=b2; }
  }
  __syncthreads();
  float mean = sh[0][0]*(1.f/DM);
  float var  = fmaxf(sh[1][0]*(1.f/DM) - mean*mean, 0.f);
  float inv  = rsqrtf(var + 1e-5f);
  #pragma unroll
  for(int j=0;j<3;j++){
    int idx = threadIdx.x + j*256;
    float o2 = (v[j]-mean)*inv*w[idx] + bias[idx];
    __nv_bfloat16 hh,ll; split_bf16(o2,hh,ll);
    pk[fbase+idx]=hh; pk[(size_t)M2*DM + fbase+idx]=ll;
  }
}

// Row LayerNorm over DM=768.
__global__ void ln_kernel(const float* __restrict__ in, const float* __restrict__ addin,
                          float* __restrict__ sumout, float* __restrict__ out,
                          __nv_bfloat16* __restrict__ pk, int planeN,
                          const float* __restrict__ w, const float* __restrict__ bias){
  int r = blockIdx.x;
  size_t base = (size_t)r*DM;
  float v[3]; float s=0.f,s2=0.f;
  #pragma unroll
  for(int j=0;j<3;j++){
    int idx = threadIdx.x + j*256;
    float t = in[base+idx];
    if(addin) t += addin[base+idx];
    v[j]=t; s+=t; s2+=t*t;
  }
  if(sumout){
    #pragma unroll
    for(int j=0;j<3;j++) sumout[base+threadIdx.x+j*256]=v[j];
  }
  #pragma unroll
  for(int o=16;o>0;o>>=1){ s+=__shfl_xor_sync(0xffffffffu,s,o); s2+=__shfl_xor_sync(0xffffffffu,s2,o); }
  __shared__ float sh[2][8];
  int wid=threadIdx.x>>5, lane=threadIdx.x&31;
  if(lane==0){ sh[0][wid]=s; sh[1][wid]=s2; }
  __syncthreads();
  if(threadIdx.x<32){
    float a = lane<8? sh[0][lane]:0.f;
    float b2= lane<8? sh[1][lane]:0.f;
    #pragma unroll
    for(int o=4;o>0;o>>=1){ a+=__shfl_xor_sync(0xffffffffu,a,o); b2+=__shfl_xor_sync(0xffffffffu,b2,o); }
    if(lane==0){ sh[0][0]=a; sh[1][0]=b2; }
  }
  __syncthreads();
  float mean = sh[0][0]*(1.f/DM);
  float var  = fmaxf(sh[1][0]*(1.f/DM) - mean*mean, 0.f);
  float inv  = rsqrtf(var + 1e-5f);
  #pragma unroll
  for(int j=0;j<3;j++){
    int idx = threadIdx.x + j*256;
    float o2 = (v[j]-mean)*inv*w[idx] + bias[idx];
    if(out) out[base+idx] = o2;
    if(pk){
      __nv_bfloat16 hh,ll; split_bf16(o2,hh,ll);
      pk[base+idx] = hh; pk[(size_t)planeN + base+idx] = ll;
    }
  }
}

// Fused final-norm + bidirectional combine.
__global__ void ln_combine_kernel(const float* __restrict__ bo, const float* __restrict__ resA,
                                  float* __restrict__ h, float* __restrict__ res,
                                  const float* __restrict__ w, const float* __restrict__ bias){
  int r = blockIdx.x;              // 0..BB*LL-1
  int b = r / LL, l = r % LL;
  size_t f  = (size_t)(b*LL + l)*DM;
  size_t rr = (size_t)((2+b)*LL + (LL-1-l))*DM;
  float vf[3], vr[3];
  float sf=0.f,s2f=0.f,sr=0.f,s2r=0.f;
  #pragma unroll
  for(int j=0;j<3;j++){
    int idx = threadIdx.x + j*256;
    float tf = bo[f+idx];  vf[j]=tf; sf+=tf; s2f+=tf*tf;
    float tr = bo[rr+idx]; vr[j]=tr; sr+=tr; s2r+=tr*tr;
  }
  #pragma unroll
  for(int o=16;o>0;o>>=1){
    sf+=__shfl_xor_sync(0xffffffffu,sf,o); s2f+=__shfl_xor_sync(0xffffffffu,s2f,o);
    sr+=__shfl_xor_sync(0xffffffffu,sr,o); s2r+=__shfl_xor_sync(0xffffffffu,s2r,o);
  }
  __shared__ float sh[4][8];
  int wid=threadIdx.x>>5, lane=threadIdx.x&31;
  if(lane==0){ sh[0][wid]=sf; sh[1][wid]=s2f; sh[2][wid]=sr; sh[3][wid]=s2r; }
  __syncthreads();
  if(threadIdx.x<32){
    float a0 = lane<8? sh[0][lane]:0.f;
    float a1 = lane<8? sh[1][lane]:0.f;
    float a2 = lane<8? sh[2][lane]:0.f;
    float a3 = lane<8? sh[3][lane]:0.f;
    #pragma unroll
    for(int o=4;o>0;o>>=1){
      a0+=__shfl_xor_sync(0xffffffffu,a0,o); a1+=__shfl_xor_sync(0xffffffffu,a1,o);
      a2+=__shfl_xor_sync(0xffffffffu,a2,o); a3+=__shfl_xor_sync(0xffffffffu,a3,o);
    }
    if(lane==0){ sh[0][0]=a0; sh[1][0]=a1; sh[2][0]=a2; sh[3][0]=a3; }
  }
  __syncthreads();
  float mf = sh[0][0]*(1.f/DM);
  float invf = rsqrtf(fmaxf(sh[1][0]*(1.f/DM)-mf*mf,0.f)+1e-5f);
  float mr = sh[2][0]*(1.f/DM);
  float invr = rsqrtf(fmaxf(sh[3][0]*(1.f/DM)-mr*mr,0.f)+1e-5f);
  #pragma unroll
  for(int j=0;j<3;j++){
    int idx = threadIdx.x + j*256;
    float of = (vf[j]-mf)*invf*w[idx] + bias[idx];
    float orr= (vr[j]-mr)*invr*w[idx] + bias[idx];
    h[f+idx]   = of + orr;
    res[f+idx] = resA[f+idx] + resA[rr+idx];
  }
}

// depthwise causal conv + silu (mirror-aware, fwd-only xz); writes fp32 xc + split-bf16 planes
__global__ void conv_silu_pack_kernel(const float* __restrict__ xz, const float* __restrict__ w,
                                      const float* __restrict__ b, float* __restrict__ xc,
                                      __nv_bfloat16* __restrict__ pk){
  int i = blockIdx.x*blockDim.x+threadIdx.x;
  if(i>=SS*LL*DI) return;
  int d=i%DI; int l=(i/DI)%LL; int s=i/(DI*LL);
  float acc = b[d];
  if(s<2){
    const float* xin = xz + (size_t)s*LL*2*DI + d;
    #pragma unroll
    for(int j=0;j<4;j++){
      int ll=l-3+j;
      if(ll>=0) acc = fmaf(w[d*4+j], xin[(size_t)ll*2*DI], acc);
    }
  } else {
    const float* xin = xz + (size_t)(s-2)*LL*2*DI + d;
    #pragma unroll
    for(int j=0;j<4;j++){
      int ll=l-3+j;
      if(ll>=0) acc = fmaf(w[d*4+j], xin[(size_t)(LL-1-ll)*2*DI], acc);
    }
  }
  float v = siluf(acc);
  xc[i] = v;
  __nv_bfloat16 hh,ll2; split_bf16(v,hh,ll2);
  pk[i]=hh; pk[(size_t)M4*DI + i]=ll2;
}

// ---------------- selective scan: pair-wise double-buffered prefetch ----------------
#define SCN_LOADP(l0, D, U, Bv, Cv, Z) do{ \
  _Pragma("unroll") \
  for(int j_=0;j_<2;j_++){ \
    int l_ = (l0)+j_; if(l_>LL-1) l_=LL-1; \
    D[j_]=dp[(size_t)l_*DI]; U[j_]=up[(size_t)l_*DI]; \
    const float* nx_ = xd + (size_t)l_*XDP; \
    Bv[j_]=*(const float4*)(nx_+DTR+4*q); \
    Cv[j_]=*(const float4*)(nx_+DTR+NS+4*q); \
    if(q==0){ int zi_ = mir? (LL-1-l_) : l_; Z[j_]=zp[(size_t)zi_*2*DI]; } \
  } }while(0)

#define SCN_STEP(lidx, cdl, cu, cB, cC, cz) do{ \
  float du_ = (cdl)*(cu); float dA0,dA1,dA2,dA3; \
  if(fast){ float e1=__expf((cdl)*a1); float e2=e1*e1,e3=e2*e1,e4=e2*e2; \
    float base_; if(q==0) base_=1.f; else if(q==1) base_=e4; else if(q==2) base_=e4*e4; else base_=e4*e4*e4; \
    dA0=base_*e1; dA1=base_*e2; dA2=base_*e3; dA3=base_*e4; } \
  else { dA0=__expf((cdl)*Ar[0]); dA1=__expf((cdl)*Ar[1]); dA2=__expf((cdl)*Ar[2]); dA3=__expf((cdl)*Ar[3]); } \
  h0=fmaf(dA0,h0,du_*(cB).x); h1=fmaf(dA1,h1,du_*(cB).y); \
  h2=fmaf(dA2,h2,du_*(cB).z); h3=fmaf(dA3,h3,du_*(cB).w); \
  float part_ = fmaf(h0,(cC).x, fmaf(h1,(cC).y, fmaf(h2,(cC).z, h3*(cC).w))); \
  part_ += __shfl_xor_sync(0xffffffffu, part_, 1); \
  part_ += __shfl_xor_sync(0xffffffffu, part_, 2); \
  if(q==0){ float yv_ = fmaf((cu), Dv, part_) * siluf(cz); \
    __nv_bfloat16 hh_,ll_; split_bf16(yv_,hh_,ll_); \
    size_t i_ = ((size_t)s*LL + (lidx))*DI + d; \
    pk[i_]=hh_; pk[(size_t)M4*DI + i_]=ll_; } }while(0)

__global__ void scan_gate_pack_kernel(const float* __restrict__ xc, const float* __restrict__ delta,
                                      const float* __restrict__ xd_all, const float* __restrict__ A_log,
                                      const float* __restrict__ Dp, const float* __restrict__ xz,
                                      __nv_bfloat16* __restrict__ pk){
  int t = blockIdx.x*blockDim.x + threadIdx.x;
  if(t >= SS*DI*4) return;
  const int q = t & 3;
  const int ch = t >> 2;
  const int d = ch % DI, s = ch / DI;
  float Ar[4];
  #pragma unroll
  for(int j=0;j<4;j++) Ar[j] = -__expf(A_log[d*NS + 4*q + j]);
  float a1 = -__expf(A_log[d*NS]);
  bool okl = true;
  #pragma unroll
  for(int j=0;j<4;j++){
    float expect = (4*q+j+1)*a1;
    okl = okl && (fabsf(Ar[j]-expect) <= 1e-5f*fabsf(expect));
  }
  unsigned bal = __ballot_sync(0xffffffffu, okl);
  int qb = (threadIdx.x & 31) & ~3;
  bool fast = (((bal >> qb) & 0xFu) == 0xFu);
  float Dv = Dp[d];
  float h0=0.f,h1=0.f,h2=0.f,h3=0.f;
  const float* up = xc    + (size_t)s*LL*DI + d;
  const float* dp = delta + (size_t)s*LL*DI + d;
  const float* xd = xd_all + (size_t)s*LL*XDP;
  const int sb = (s<2)? s : (s-2);
  const float* zp = xz + (size_t)sb*LL*2*DI + DI + d;
  const bool mir = (s>=2);

  float d0[2],u0[2],z0[2],d1[2],u1[2],z1[2];
  float4 B0[2],C0[2],B1[2],C1[2];
  z0[0]=z0[1]=0.f; z1[0]=z1[1]=0.f;
  SCN_LOADP(0, d0,u0,B0,C0,z0);
  for(int base=0; base<LL; base+=4){
    SCN_LOADP(base+2, d1,u1,B1,C1,z1);
    SCN_STEP(base+0, d0[0],u0[0],B0[0],C0[0],z0[0]);
    SCN_STEP(base+1, d0[1],u0[1],B0[1],C0[1],z0[1]);
    SCN_LOADP(base+4, d0,u0,B0,C0,z0);
    SCN_STEP(base+2, d1[0],u1[0],B1[0],C1[0],z1[0]);
    SCN_STEP(base+3, d1[1],u1[1],B1[1],C1[1],z1[1]);
  }
}

// a*silu(gate) -> packed split-bf16 (for fc2 GEMM input)
__global__ void fc_gate_pack_kernel(const float* __restrict__ big, __nv_bfloat16* __restrict__ pk){
  int i=blockIdx.x*blockDim.x+threadIdx.x;
  if(i>=SS*LL*DI) return;
  int r=i/DI, j=i%DI;
  float a = big[(size_t)r*2*DI + j];
  float b = big[(size_t)r*2*DI + DI + j];
  float v = a*siluf(b);
  __nv_bfloat16 hh,ll; split_bf16(v,hh,ll);
  pk[i]=hh; pk[(size_t)M4*DI + i]=ll;
}

__global__ void mean_kernel(const float* __restrict__ fin, float* __restrict__ out){
  int i=blockIdx.x*blockDim.x+threadIdx.x;
  if(i>=BB*DM) return;
  int b=i/DM, j=i%DM;
  float s=0.f;
  for(int l=0;l<LL;l++) s += fin[((size_t)(b*LL+l))*DM+j];
  out[i] = s*(1.f/LL);
}

// ---------------- fused weight pack: ALL weights, BOTH layers, one launch ----------------
#define WPA (2*DI*DM)     // in_proj / fc1 per-layer elems
#define WPB (DM*DI)       // out_proj / fc2 per-layer elems
#define WPC (XDP*DI)      // padded x_proj per-layer elems
#define WP_TOTAL (NLAYER*(2*WPA + 2*WPB + WPC))

__global__ void wpack_all_kernel(const float* __restrict__ in_proj, const float* __restrict__ fc1,
                                 const float* __restrict__ out_proj, const float* __restrict__ fc2,
                                 const float* __restrict__ x_proj,
                                 __nv_bfloat16* __restrict__ pw_in, __nv_bfloat16* __restrict__ pw_fc1,
                                 __nv_bfloat16* __restrict__ pw_out, __nv_bfloat16* __restrict__ pw_fc2,
                                 __nv_bfloat16* __restrict__ pw_xp){
  int i = blockIdx.x*blockDim.x+threadIdx.x;
  if(i >= WP_TOTAL) return;
  float v; __nv_bfloat16* dst; size_t off; size_t plane;
  if(i < NLAYER*WPA){                              // in_proj
    int li = i / WPA, j = i % WPA;
    v = in_proj[(size_t)li*WPA + j];
    dst = pw_in + (size_t)li*2*WPA; off = j; plane = WPA;
  } else if(i < 2*NLAYER*WPA){                     // fc1
    int k = i - NLAYER*WPA;
    int li = k / WPA, j = k % WPA;
    v = fc1[(size_t)li*WPA + j];
    dst = pw_fc1 + (size_t)li*2*WPA; off = j; plane = WPA;
  } else if(i < 2*NLAYER*WPA + NLAYER*WPB){        // out_proj
    int k = i - 2*NLAYER*WPA;
    int li = k / WPB, j = k % WPB;
    v = out_proj[(size_t)li*WPB + j];
    dst = pw_out + (size_t)li*2*WPB; off = j; plane = WPB;
  } else if(i < 2*NLAYER*WPA + 2*NLAYER*WPB){      // fc2
    int k = i - 2*NLAYER*WPA - NLAYER*WPB;
    int li = k / WPB, j = k % WPB;
    v = fc2[(size_t)li*WPB + j];
    dst = pw_fc2 + (size_t)li*2*WPB; off = j; plane = WPB;
  } else {                                         // x_proj (padded)
    int k = i - 2*NLAYER*WPA - 2*NLAYER*WPB;
    int li = k / WPC, j = k % WPC;
    int row = j / DI, col = j % DI;
    v = (row < XD) ? x_proj[(size_t)li*XD*DI + (size_t)row*DI + col] : 0.f;
    dst = pw_xp + (size_t)li*2*WPC; off = j; plane = WPC;
  }
  __nv_bfloat16 hh,ll; split_bf16(v,hh,ll);
  dst[off] = hh; dst[plane + off] = ll;
}

// ---------------- HMMA (mma.sync bf16, split 3-pass) GEMM, BK=32 ----------------
__device__ __forceinline__ uint32_t smem_u32(const void* p){
  uint32_t a;
  asm("{ .reg .u64 t; cvta.to.shared.u64 t, %1; cvt.u32.u64 %0, t; }" : "=r"(a) : "l"(p));
  return a;
}
#define LDSM4(r, addr) \
  asm volatile("ldmatrix.sync.aligned.m8n8.x4.shared.b16 {%0,%1,%2,%3}, [%4];" \
    : "=r"((r)[0]),"=r"((r)[1]),"=r"((r)[2]),"=r"((r)[3]) : "r"(addr))
#define MMA16(d, a, b0, b1) \
  asm volatile("mma.sync.aligned.m16n8k16.row.col.f32.bf16.bf16.f32 " \
    "{%0,%1,%2,%3}, {%4,%5,%6,%7}, {%8,%9}, {%0,%1,%2,%3};" \
    : "+f"((d)[0]),"+f"((d)[1]),"+f"((d)[2]),"+f"((d)[3]) \
    : "r"((a)[0]),"r"((a)[1]),"r"((a)[2]),"r"((a)[3]), "r"(b0),"r"(b1))
#define CPA16(dst,src) asm volatile("cp.async.cg.shared.global [%0], [%1], 16;" :: "r"(dst), "l"(src))
#define CPCOMMIT() asm volatile("cp.async.commit_group;" ::: "memory")
#define CPWAIT1()  asm volatile("cp.async.wait_group 1;" ::: "memory")

// plane = 128 rows x 64B (32 bf16); stage = 4 planes (A_hi, A_lo, B_hi, B_lo)
#define HM_PLANE_BYTES 8192
#define HM_STAGE_BYTES 32768
#define HM_NSTG 3
#define HM_SMEM (HM_NSTG*HM_STAGE_BYTES)

__device__ __forceinline__ uint32_t hm_off(int row, int half){
  // half in 0..3 (16B chunks within the 64B row); 8-row groups of 512B
  return (uint32_t)((row>>3)*512 + (row&7)*16 + half*128);
}

__global__ void __launch_bounds__(256,2) mm_hmma(
    int K, int N,
    const __nv_bfloat16* __restrict__ Ap,
    const __nv_bfloat16* __restrict__ Bp,
    float* __restrict__ C)
{
  extern __shared__ __align__(128) char smem_[];
  const int tid = threadIdx.x, wid = tid>>5, lane = tid&31;
  const int bm = blockIdx.y, bn = blockIdx.x;
  const size_t aplane = (size_t)gridDim.y*128*K;
  const size_t bplane = (size_t)N*K;
  uint32_t sbase = smem_u32(smem_);

  // loader: 512 16B-chunks per plane; thread handles chunks tid and tid+256
  const int r0 = tid>>2,        h0 = tid&3;
  const int r1 = (tid+256)>>2,  h1 = tid&3;   // rows 64..127
  const __nv_bfloat16* gA0 = Ap + (size_t)(bm*128 + r0)*K + h0*8;
  const __nv_bfloat16* gA1 = Ap + (size_t)(bm*128 + r1)*K + h1*8;
  const __nv_bfloat16* gB0 = Bp + (size_t)(bn*128 + r0)*K + h0*8;
  const __nv_bfloat16* gB1 = Bp + (size_t)(bn*128 + r1)*K + h1*8;
  const uint32_t s0 = sbase + hm_off(r0, h0);
  const uint32_t s1 = sbase + hm_off(r1, h1);

  const int T = K>>5;
  const int warp_m = wid>>1, warp_n = wid&1;
  const int lq = lane&15, lh2 = lane>>4;
  uint32_t aoff[2], boff[4];
  #pragma unroll
  for(int mi=0;mi<2;mi++) aoff[mi] = hm_off(warp_m*32+mi*16+lq, lh2);
  #pragma unroll
  for(int j=0;j<4;j++)    boff[j]  = hm_off(warp_n*64+j*16+lq, lh2);

  float acc[2][8][4];
  #pragma unroll
  for(int mi=0;mi<2;mi++)
    #pragma unroll
    for(int f=0;f<8;f++)
      #pragma unroll
      for(int q=0;q<4;q++) acc[mi][f][q]=0.f;

  // prologue: prefetch 2 stages (BK=32 each)
  #pragma unroll
  for(int t=0;t<2;t++){
    uint32_t d = (uint32_t)t*HM_STAGE_BYTES;
    const __nv_bfloat16* a0 = gA0 + t*32; const __nv_bfloat16* a1 = gA1 + t*32;
    const __nv_bfloat16* b0 = gB0 + t*32; const __nv_bfloat16* b1 = gB1 + t*32;
    CPA16(s0+d,                    a0);          CPA16(s1+d,                    a1);
    CPA16(s0+d+HM_PLANE_BYTES,     a0+aplane);   CPA16(s1+d+HM_PLANE_BYTES,     a1+aplane);
    CPA16(s0+d+2*HM_PLANE_BYTES,   b0);          CPA16(s1+d+2*HM_PLANE_BYTES,   b1);
    CPA16(s0+d+3*HM_PLANE_BYTES,   b0+bplane);   CPA16(s1+d+3*HM_PLANE_BYTES,   b1+bplane);
    CPCOMMIT();
  }

  int stg = 0;
  for(int t=0;t<T;t++){
    CPWAIT1();
    __syncthreads();
    uint32_t st_ = sbase + (uint32_t)stg*HM_STAGE_BYTES;
    #pragma unroll
    for(int kc=0;kc<2;kc++){
      uint32_t ko = (uint32_t)kc*256;   // half += 2 per k-chunk
      uint32_t ah[2][4], al[2][4], bb[4][4];
      #pragma unroll
      for(int mi=0;mi<2;mi++){
        LDSM4(ah[mi], st_ + aoff[mi] + ko);
        LDSM4(al[mi], st_ + HM_PLANE_BYTES + aoff[mi] + ko);
      }
      #pragma unroll
      for(int j=0;j<4;j++) LDSM4(bb[j], st_ + 2*HM_PLANE_BYTES + boff[j] + ko);
      #pragma unroll
      for(int mi=0;mi<2;mi++){
        #pragma unroll
        for(int f=0;f<8;f++){
          const int j=f>>1, sel=f&1;
          MMA16(acc[mi][f], ah[mi], bb[j][sel], bb[j][sel+2]);
          MMA16(acc[mi][f], al[mi], bb[j][sel], bb[j][sel+2]);
        }
      }
      #pragma unroll
      for(int j=0;j<4;j++) LDSM4(bb[j], st_ + 3*HM_PLANE_BYTES + boff[j] + ko);
      #pragma unroll
      for(int mi=0;mi<2;mi++){
        #pragma unroll
        for(int f=0;f<8;f++){
          const int j=f>>1, sel=f&1;
          MMA16(acc[mi][f], ah[mi], bb[j][sel], bb[j][sel+2]);
        }
      }
    }
    int tn = t+2;
    if(tn < T){
      int ws = stg+2; if(ws>=HM_NSTG) ws-=HM_NSTG;
      uint32_t d = (uint32_t)ws*HM_STAGE_BYTES;
      const __nv_bfloat16* a0 = gA0 + tn*32; const __nv_bfloat16* a1 = gA1 + tn*32;
      const __nv_bfloat16* b0 = gB0 + tn*32; const __nv_bfloat16* b1 = gB1 + tn*32;
      CPA16(s0+d,                    a0);          CPA16(s1+d,                    a1);
      CPA16(s0+d+HM_PLANE_BYTES,     a0+aplane);   CPA16(s1+d+HM_PLANE_BYTES,     a1+aplane);
      CPA16(s0+d+2*HM_PLANE_BYTES,   b0);          CPA16(s1+d+2*HM_PLANE_BYTES,   b1);
      CPA16(s0+d+3*HM_PLANE_BYTES,   b0+bplane);   CPA16(s1+d+3*HM_PLANE_BYTES,   b1+bplane);
    }
    CPCOMMIT();
    stg++; if(stg>=HM_NSTG) stg=0;
  }

  const int tr = lane>>2, tc = (lane&3)*2;
  const int row0 = bm*128 + warp_m*32;
  const int col0 = bn*128 + warp_n*64;
  #pragma unroll
  for(int mi=0;mi<2;mi++){
    #pragma unroll
    for(int f=0;f<8;f++){
      float* c0 = C + (size_t)(row0+mi*16+tr)*N + col0 + f*8 + tc;
      float2 v0; v0.x=acc[mi][f][0]; v0.y=acc[mi][f][1];
      float2 v1; v1.x=acc[mi][f][2]; v1.y=acc[mi][f][3];
      *(float2*)c0 = v0;
      *(float2*)(c0 + 8*(size_t)N) = v1;
    }
  }
}

// ---------------- fallback FFMA GEMM (delta: K=48) ----------------
template<int BM,int BN,int TM,int TN,int BK>
__global__ void __launch_bounds__(256) gemm_nt(
    int M,int N,int K,int lda,
    const float* __restrict__ A, const float* __restrict__ Bw,
    float* __restrict__ C, const float* __restrict__ bias, int act)
{
  __shared__ float As[BK][BM];
  __shared__ float Bs[BK][BN];
  const int t  = threadIdx.x;
  const int bm = blockIdx.y*BM, bn = blockIdx.x*BN;
  const int TCOL = BN/TN;
  const int tx = t % TCOL, ty = t / TCOL;
  const int KQ = BK/4;
  float acc[TM][TN];
  #pragma unroll
  for(int i=0;i<TM;i++)
    #pragma unroll
    for(int j=0;j<TN;j++) acc[i][j]=0.f;

  for(int k0=0;k0<K;k0+=BK){
    for(int i=t;i<BM*KQ;i+=256){
      int row = i/KQ, kq = (i%KQ)*4;
      float4 v = *(const float4*)(A + (size_t)(bm+row)*lda + k0 + kq);
      As[kq][row]=v.x; As[kq+1][row]=v.y; As[kq+2][row]=v.z; As[kq+3][row]=v.w;
    }
    for(int i=t;i<BN*KQ;i+=256){
      int row = i/KQ, kq = (i%KQ)*4;
      int gn = bn+row;
      float4 v = make_float4(0.f,0.f,0.f,0.f);
      if(gn<N) v = *(const float4*)(Bw + (size_t)gn*K + k0 + kq);
      Bs[kq][row]=v.x; Bs[kq+1][row]=v.y; Bs[kq+2][row]=v.z; Bs[kq+3][row]=v.w;
    }
    __syncthreads();
    #pragma unroll
    for(int kk=0;kk<BK;kk++){
      float a[TM], b[TN];
      #pragma unroll
      for(int i=0;i<TM;i++) a[i]=As[kk][ty*TM+i];
      #pragma unroll
      for(int j=0;j<TN;j++) b[j]=Bs[kk][tx*TN+j];
      #pragma unroll
      for(int i=0;i<TM;i++)
        #pragma unroll
        for(int j=0;j<TN;j++) acc[i][j] = fmaf(a[i],b[j],acc[i][j]);
    }
    __syncthreads();
  }
  #pragma unroll
  for(int i=0;i<TM;i++){
    int gm = bm + ty*TM + i;
    #pragma unroll
    for(int j=0;j<TN;j++){
      int gn = bn + tx*TN + j;
      if(gn<N){
        float c = acc[i][j];
        if(bias) c += bias[gn];
        if(act==1) c = (c>20.f)? c : log1pf(__expf(c));
        C[(size_t)gm*N + gn] = c;
      }
    }
  }
}

// ---------------- launcher ----------------
extern "C" void kernel_launch(void* const* d_in, const int* in_sizes, int n_in,
                              void* d_out, int out_size){
  const int*   ids    = (const int*)  d_in[0];
  const float* emb    = (const float*)d_in[1];
  const float* norm_w = (const float*)d_in[2];
  const float* norm_b = (const float*)d_in[3];
  const float* in_proj= (const float*)d_in[4];
  const float* conv_w = (const float*)d_in[5];
  const float* conv_b = (const float*)d_in[6];
  const float* x_proj = (const float*)d_in[7];
  const float* dt_w   = (const float*)d_in[8];
  const float* dt_b   = (const float*)d_in[9];
  const float* A_log  = (const float*)d_in[10];
  const float* Dw     = (const float*)d_in[11];
  const float* out_proj=(const float*)d_in[12];
  const float* norm2_w= (const float*)d_in[13];
  const float* norm2_b= (const float*)d_in[14];
  const float* fc1    = (const float*)d_in[15];
  const float* fc2    = (const float*)d_in[16];
  const float* normf_w= (const float*)d_in[17];
  const float* normf_b= (const float*)d_in[18];
  float* out = (float*)d_out;

  float *p_h,*p_res,*p_resA,*p_xz,*p_xc,*p_xdbl,*p_delta,*p_bo,*p_fin;
  __nv_bfloat16 *pa768,*pa1536,*pw_in,*pw_fc1,*pw_out,*pw_fc2,*pw_xp;
  cudaGetSymbolAddress((void**)&p_h,    g_h);
  cudaGetSymbolAddress((void**)&p_res,  g_res);
  cudaGetSymbolAddress((void**)&p_resA, g_resA);
  cudaGetSymbolAddress((void**)&p_xz,   g_xz);
  cudaGetSymbolAddress((void**)&p_xc,   g_xc);
  cudaGetSymbolAddress((void**)&p_xdbl, g_xdbl);
  cudaGetSymbolAddress((void**)&p_delta,g_delta);
  cudaGetSymbolAddress((void**)&p_bo,   g_bo);
  cudaGetSymbolAddress((void**)&p_fin,  g_fin);
  cudaGetSymbolAddress((void**)&pa768,  g_pa768);
  cudaGetSymbolAddress((void**)&pa1536, g_pa1536);
  cudaGetSymbolAddress((void**)&pw_in,  g_pw_in);
  cudaGetSymbolAddress((void**)&pw_fc1, g_pw_fc1);
  cudaGetSymbolAddress((void**)&pw_out, g_pw_out);
  cudaGetSymbolAddress((void**)&pw_fc2, g_pw_fc2);
  cudaGetSymbolAddress((void**)&pw_xp,  g_pw_xp);

  cudaFuncSetAttribute(mm_hmma, cudaFuncAttributeMaxDynamicSharedMemorySize, HM_SMEM);

  const int TP=256;
  // Launch order tuned so the ncu-captured launch (my #4) is mm_hmma(in_proj L0).
  wpack_all_kernel<<<(WP_TOTAL+TP-1)/TP,TP>>>(in_proj, fc1, out_proj, fc2, x_proj,
                                              pw_in, pw_fc1, pw_out, pw_fc2, pw_xp);           // 1
  embed_kernel<<<(BB*LL*DM+TP-1)/TP,TP>>>(ids, emb, p_h);                                     // 2
  aug_ln_pack_kernel<<<BB*LL,256>>>(p_h, p_res, p_resA, pa768, norm_w, norm_b, 0);            // 3
  { dim3 g(2*DI/128, M2/128); mm_hmma<<<g,256,HM_SMEM>>>(DM, 2*DI, pa768, pw_in, p_xz); }     // 4 <- profile me

  for(int li=0; li<NLAYER; li++){
    const float* cw = conv_w  + (size_t)li*DI*4;
    const float* cb = conv_b  + (size_t)li*DI;
    const float* dw = dt_w    + (size_t)li*DI*DTR;
    const float* db = dt_b    + (size_t)li*DI;
    const float* al = A_log   + (size_t)li*DI*NS;
    const float* Dl = Dw      + (size_t)li*DI;
    const float* n2w= norm2_w + (size_t)li*DM;
    const float* n2b= norm2_b + (size_t)li*DM;
    const __nv_bfloat16* wF1 = pw_fc1 + (size_t)li*2*(2*DI)*DM;
    const __nv_bfloat16* wOu = pw_out + (size_t)li*2*DM*DI;
    const __nv_bfloat16* wF2 = pw_fc2 + (size_t)li*2*DM*DI;
    const __nv_bfloat16* wXp = pw_xp  + (size_t)li*2*XDP*DI;

    if(li==1){
      aug_ln_pack_kernel<<<BB*LL,256>>>(p_h, p_res, p_resA, pa768,
                                        norm_w + (size_t)1*DM, norm_b + (size_t)1*DM, 1);
      dim3 g(2*DI/128, M2/128);
      mm_hmma<<<g,256,HM_SMEM>>>(DM, 2*DI, pa768, pw_in + (size_t)1*2*(2*DI)*DM, p_xz);
    }

    // conv + silu + split-pack xc (mirror-aware, reads fwd-only xz)
    conv_silu_pack_kernel<<<(SS*LL*DI+TP-1)/TP,TP>>>(p_xz, cw, cb, p_xc, pa1536);

    // x_dbl(padded) = xc @ x_proj_pad^T  (HMMA, N=128)
    { dim3 g(1, M4/128); mm_hmma<<<g,256,HM_SMEM>>>(DI, XDP, pa1536, wXp, p_xdbl); }

    // delta = softplus(dt @ dt_w^T + dt_b)  (K=48, lda=XDP)
    { dim3 g(DI/128, M4/128); gemm_nt<128,128,8,8,16><<<g,256>>>(M4, DI, DTR, XDP, p_xdbl, dw, p_delta, db, 1); }

    // selective scan + gate + pack (feeds out_proj)
    scan_gate_pack_kernel<<<(SS*DI*4+127)/128,128>>>(p_xc, p_delta, p_xdbl, al, Dl, p_xz, pa1536);

    // mixer_out = y @ out_proj^T (HMMA)
    { dim3 g(DM/128, M4/128); mm_hmma<<<g,256,HM_SMEM>>>(DI, DM, pa1536, wOu, p_bo); }

    // res += mixer_out ; x2 = LN(res, norm2) -> packed (feeds fc1 only)
    ln_kernel<<<M4,256>>>(p_bo, p_resA, p_resA, nullptr, pa768, M4*DM, n2w, n2b);

    // fc1 (HMMA)
    { dim3 g(2*DI/128, M4/128); mm_hmma<<<g,256,HM_SMEM>>>(DM, 2*DI, pa768, wF1, p_xz); }

    // gated MLP -> packed (feeds fc2 only)
    fc_gate_pack_kernel<<<(SS*LL*DI+TP-1)/TP,TP>>>(p_xz, pa1536);

    // fc2 (HMMA)
    { dim3 g(DM/128, M4/128); mm_hmma<<<g,256,HM_SMEM>>>(DI, DM, pa1536, wF2, p_bo); }

    // fused final-norm + combine
    ln_combine_kernel<<<BB*LL,256>>>(p_bo, p_resA, p_h, p_res, normf_w, normf_b);
  }

  ln_kernel<<<BB*LL,256>>>(p_h, p_res, nullptr, p_fin, nullptr, 0, normf_w, normf_b);
  mean_kernel<<<(BB*DM+TP-1)/TP,TP>>>(p_fin, out);
}

// round 15
// speedup vs baseline: 1.1087x; 1.1087x over previous
#include <cuda_runtime.h>
#include <cuda_bf16.h>
#include <math.h>
#include <stdint.h>

#define BB 2
#define LL 1024
#define DM 768
#define NLAYER 2
#define DI 1536
#define NS 16
#define DTR 48
#define XD 80           // DTR + 2*NS
#define XDP 128         // padded x_dbl width
#define SS 4            // augmented batch: [fwd b0, fwd b1, bwd b0, bwd b1]
#define M4 (SS*LL)      // 4096 rows (augmented)
#define M2 (2*LL)       // 2048 rows (fwd only, in_proj GEMM)

// ---------------- scratch (static __device__, no allocation) ----------------
__device__ __align__(128) float g_h[BB*LL*DM];
__device__ __align__(128) float g_res[BB*LL*DM];
__device__ __align__(128) float g_resA[SS*LL*DM];
__device__ __align__(128) float g_xz[M2*2*DI];          // fwd only
__device__ __align__(128) float g_xc[SS*LL*DI];
__device__ __align__(128) float g_xdbl[M4*XDP];
__device__ __align__(128) float g_delta[SS*LL*DI];
__device__ __align__(128) float g_bo[SS*LL*DM];
__device__ __align__(128) float g_bo2[SS*LL*DM];        // split-K partial
__device__ __align__(128) float g_fin[BB*LL*DM];

// split-bf16 activation/weight planes: [hi plane][lo plane], row-major
__device__ __align__(128) __nv_bfloat16 g_pa768 [2*M4*DM];
__device__ __align__(128) __nv_bfloat16 g_pa1536[2*M4*DI];
__device__ __align__(128) __nv_bfloat16 g_pw_in [NLAYER*2*(2*DI)*DM];
__device__ __align__(128) __nv_bfloat16 g_pw_fc1[NLAYER*2*(2*DI)*DM];
__device__ __align__(128) __nv_bfloat16 g_pw_out[NLAYER*2*DM*DI];
__device__ __align__(128) __nv_bfloat16 g_pw_fc2[NLAYER*2*DM*DI];
__device__ __align__(128) __nv_bfloat16 g_pw_xp [NLAYER*2*XDP*DI];

__device__ __forceinline__ float siluf(float x){ return x/(1.f+__expf(-x)); }

__device__ __forceinline__ void split_bf16(float v, __nv_bfloat16& h, __nv_bfloat16& l){
  h = __float2bfloat16(v);
  l = __float2bfloat16(v - __bfloat162float(h));
}

// ---------------- elementwise kernels ----------------
__global__ void embed_kernel(const int* __restrict__ ids, const float* __restrict__ emb,
                             float* __restrict__ out){
  int i = blockIdx.x*blockDim.x+threadIdx.x;
  if(i>=BB*LL*DM) return;
  int d=i%DM; int t=i/DM;
  out[i] = emb[(size_t)ids[t]*DM + d];
}

// Fused: v = h (+res); resA[fwd]=resA[bwd-mirror]=v; LN(v) -> split-bf16 planes (FWD rows only).
__global__ void aug_ln_pack_kernel(const float* __restrict__ h, const float* __restrict__ res,
                                   float* __restrict__ resA, __nv_bfloat16* __restrict__ pk,
                                   const float* __restrict__ w, const float* __restrict__ bias,
                                   int use_res){
  int r = blockIdx.x;              // 0 .. BB*LL-1
  int b = r / LL, l = r % LL;
  size_t fbase = (size_t)(b*LL + l)*DM;
  size_t rbase = (size_t)((2+b)*LL + (LL-1-l))*DM;
  float v[3]; float s=0.f,s2=0.f;
  #pragma unroll
  for(int j=0;j<3;j++){
    int idx = threadIdx.x + j*256;
    float t = h[fbase+idx];
    if(use_res) t += res[fbase+idx];
    v[j]=t; s+=t; s2+=t*t;
    resA[fbase+idx]=t; resA[rbase+idx]=t;
  }
  #pragma unroll
  for(int o=16;o>0;o>>=1){ s+=__shfl_xor_sync(0xffffffffu,s,o); s2+=__shfl_xor_sync(0xffffffffu,s2,o); }
  __shared__ float sh[2][8];
  int wid=threadIdx.x>>5, lane=threadIdx.x&31;
  if(lane==0){ sh[0][wid]=s; sh[1][wid]=s2; }
  __syncthreads();
  if(threadIdx.x<32){
    float a = lane<8? sh[0][lane]:0.f;
    float b2= lane<8? sh[1][lane]:0.f;
    #pragma unroll
    for(int o=4;o>0;o>>=1){ a+=__shfl_xor_sync(0xffffffffu,a,o); b2+=__shfl_xor_sync(0xffffffffu,b2,o); }
    if(lane==0){ sh[0][0]=a; sh[1][0]=b2; }
  }
  __syncthreads();
  float mean = sh[0][0]*(1.f/DM);
  float var  = fmaxf(sh[1][0]*(1.f/DM) - mean*mean, 0.f);
  float inv  = rsqrtf(var + 1e-5f);
  #pragma unroll
  for(int j=0;j<3;j++){
    int idx = threadIdx.x + j*256;
    float o2 = (v[j]-mean)*inv*w[idx] + bias[idx];
    __nv_bfloat16 hh,ll; split_bf16(o2,hh,ll);
    pk[fbase+idx]=hh; pk[(size_t)M2*DM + fbase+idx]=ll;
  }
}

// Row LayerNorm over DM=768. Optional second input (split-K partial), pre-add,
// fp32 sum writeback, fp32 out, packed split-bf16 out.
__global__ void ln_kernel(const float* __restrict__ in, const float* __restrict__ in2,
                          const float* __restrict__ addin,
                          float* __restrict__ sumout, float* __restrict__ out,
                          __nv_bfloat16* __restrict__ pk, int planeN,
                          const float* __restrict__ w, const float* __restrict__ bias){
  int r = blockIdx.x;
  size_t base = (size_t)r*DM;
  float v[3]; float s=0.f,s2=0.f;
  #pragma unroll
  for(int j=0;j<3;j++){
    int idx = threadIdx.x + j*256;
    float t = in[base+idx];
    if(in2)   t += in2[base+idx];
    if(addin) t += addin[base+idx];
    v[j]=t; s+=t; s2+=t*t;
  }
  if(sumout){
    #pragma unroll
    for(int j=0;j<3;j++) sumout[base+threadIdx.x+j*256]=v[j];
  }
  #pragma unroll
  for(int o=16;o>0;o>>=1){ s+=__shfl_xor_sync(0xffffffffu,s,o); s2+=__shfl_xor_sync(0xffffffffu,s2,o); }
  __shared__ float sh[2][8];
  int wid=threadIdx.x>>5, lane=threadIdx.x&31;
  if(lane==0){ sh[0][wid]=s; sh[1][wid]=s2; }
  __syncthreads();
  if(threadIdx.x<32){
    float a = lane<8? sh[0][lane]:0.f;
    float b2= lane<8? sh[1][lane]:0.f;
    #pragma unroll
    for(int o=4;o>0;o>>=1){ a+=__shfl_xor_sync(0xffffffffu,a,o); b2+=__shfl_xor_sync(0xffffffffu,b2,o); }
    if(lane==0){ sh[0][0]=a; sh[1][0]=b2; }
  }
  __syncthreads();
  float mean = sh[0][0]*(1.f/DM);
  float var  = fmaxf(sh[1][0]*(1.f/DM) - mean*mean, 0.f);
  float inv  = rsqrtf(var + 1e-5f);
  #pragma unroll
  for(int j=0;j<3;j++){
    int idx = threadIdx.x + j*256;
    float o2 = (v[j]-mean)*inv*w[idx] + bias[idx];
    if(out) out[base+idx] = o2;
    if(pk){
      __nv_bfloat16 hh,ll; split_bf16(o2,hh,ll);
      pk[base+idx] = hh; pk[(size_t)planeN + base+idx] = ll;
    }
  }
}

// Fused final-norm + bidirectional combine; bo = bo1 + bo2 (split-K partials).
__global__ void ln_combine_kernel(const float* __restrict__ bo, const float* __restrict__ bo2,
                                  const float* __restrict__ resA,
                                  float* __restrict__ h, float* __restrict__ res,
                                  const float* __restrict__ w, const float* __restrict__ bias){
  int r = blockIdx.x;              // 0..BB*LL-1
  int b = r / LL, l = r % LL;
  size_t f  = (size_t)(b*LL + l)*DM;
  size_t rr = (size_t)((2+b)*LL + (LL-1-l))*DM;
  float vf[3], vr[3];
  float sf=0.f,s2f=0.f,sr=0.f,s2r=0.f;
  #pragma unroll
  for(int j=0;j<3;j++){
    int idx = threadIdx.x + j*256;
    float tf = bo[f+idx]  + bo2[f+idx];   vf[j]=tf; sf+=tf; s2f+=tf*tf;
    float tr = bo[rr+idx] + bo2[rr+idx];  vr[j]=tr; sr+=tr; s2r+=tr*tr;
  }
  #pragma unroll
  for(int o=16;o>0;o>>=1){
    sf+=__shfl_xor_sync(0xffffffffu,sf,o); s2f+=__shfl_xor_sync(0xffffffffu,s2f,o);
    sr+=__shfl_xor_sync(0xffffffffu,sr,o); s2r+=__shfl_xor_sync(0xffffffffu,s2r,o);
  }
  __shared__ float sh[4][8];
  int wid=threadIdx.x>>5, lane=threadIdx.x&31;
  if(lane==0){ sh[0][wid]=sf; sh[1][wid]=s2f; sh[2][wid]=sr; sh[3][wid]=s2r; }
  __syncthreads();
  if(threadIdx.x<32){
    float a0 = lane<8? sh[0][lane]:0.f;
    float a1 = lane<8? sh[1][lane]:0.f;
    float a2 = lane<8? sh[2][lane]:0.f;
    float a3 = lane<8? sh[3][lane]:0.f;
    #pragma unroll
    for(int o=4;o>0;o>>=1){
      a0+=__shfl_xor_sync(0xffffffffu,a0,o); a1+=__shfl_xor_sync(0xffffffffu,a1,o);
      a2+=__shfl_xor_sync(0xffffffffu,a2,o); a3+=__shfl_xor_sync(0xffffffffu,a3,o);
    }
    if(lane==0){ sh[0][0]=a0; sh[1][0]=a1; sh[2][0]=a2; sh[3][0]=a3; }
  }
  __syncthreads();
  float mf = sh[0][0]*(1.f/DM);
  float invf = rsqrtf(fmaxf(sh[1][0]*(1.f/DM)-mf*mf,0.f)+1e-5f);
  float mr = sh[2][0]*(1.f/DM);
  float invr = rsqrtf(fmaxf(sh[3][0]*(1.f/DM)-mr*mr,0.f)+1e-5f);
  #pragma unroll
  for(int j=0;j<3;j++){
    int idx = threadIdx.x + j*256;
    float of = (vf[j]-mf)*invf*w[idx] + bias[idx];
    float orr= (vr[j]-mr)*invr*w[idx] + bias[idx];
    h[f+idx]   = of + orr;
    res[f+idx] = resA[f+idx] + resA[rr+idx];
  }
}

// depthwise causal conv + silu (mirror-aware, fwd-only xz); writes fp32 xc + split-bf16 planes
__global__ void conv_silu_pack_kernel(const float* __restrict__ xz, const float* __restrict__ w,
                                      const float* __restrict__ b, float* __restrict__ xc,
                                      __nv_bfloat16* __restrict__ pk){
  int i = blockIdx.x*blockDim.x+threadIdx.x;
  if(i>=SS*LL*DI) return;
  int d=i%DI; int l=(i/DI)%LL; int s=i/(DI*LL);
  float acc = b[d];
  if(s<2){
    const float* xin = xz + (size_t)s*LL*2*DI + d;
    #pragma unroll
    for(int j=0;j<4;j++){
      int ll=l-3+j;
      if(ll>=0) acc = fmaf(w[d*4+j], xin[(size_t)ll*2*DI], acc);
    }
  } else {
    const float* xin = xz + (size_t)(s-2)*LL*2*DI + d;
    #pragma unroll
    for(int j=0;j<4;j++){
      int ll=l-3+j;
      if(ll>=0) acc = fmaf(w[d*4+j], xin[(size_t)(LL-1-ll)*2*DI], acc);
    }
  }
  float v = siluf(acc);
  xc[i] = v;
  __nv_bfloat16 hh,ll2; split_bf16(v,hh,ll2);
  pk[i]=hh; pk[(size_t)M4*DI + i]=ll2;
}

// ---------------- selective scan: pair-wise double-buffered prefetch ----------------
#define SCN_LOADP(l0, D, U, Bv, Cv, Z) do{ \
  _Pragma("unroll") \
  for(int j_=0;j_<2;j_++){ \
    int l_ = (l0)+j_; if(l_>LL-1) l_=LL-1; \
    D[j_]=dp[(size_t)l_*DI]; U[j_]=up[(size_t)l_*DI]; \
    const float* nx_ = xd + (size_t)l_*XDP; \
    Bv[j_]=*(const float4*)(nx_+DTR+4*q); \
    Cv[j_]=*(const float4*)(nx_+DTR+NS+4*q); \
    if(q==0){ int zi_ = mir? (LL-1-l_) : l_; Z[j_]=zp[(size_t)zi_*2*DI]; } \
  } }while(0)

#define SCN_STEP(lidx, cdl, cu, cB, cC, cz) do{ \
  float du_ = (cdl)*(cu); float dA0,dA1,dA2,dA3; \
  if(fast){ float e1=__expf((cdl)*a1); float e2=e1*e1,e3=e2*e1,e4=e2*e2; \
    float base_; if(q==0) base_=1.f; else if(q==1) base_=e4; else if(q==2) base_=e4*e4; else base_=e4*e4*e4; \
    dA0=base_*e1; dA1=base_*e2; dA2=base_*e3; dA3=base_*e4; } \
  else { dA0=__expf((cdl)*Ar[0]); dA1=__expf((cdl)*Ar[1]); dA2=__expf((cdl)*Ar[2]); dA3=__expf((cdl)*Ar[3]); } \
  h0=fmaf(dA0,h0,du_*(cB).x); h1=fmaf(dA1,h1,du_*(cB).y); \
  h2=fmaf(dA2,h2,du_*(cB).z); h3=fmaf(dA3,h3,du_*(cB).w); \
  float part_ = fmaf(h0,(cC).x, fmaf(h1,(cC).y, fmaf(h2,(cC).z, h3*(cC).w))); \
  part_ += __shfl_xor_sync(0xffffffffu, part_, 1); \
  part_ += __shfl_xor_sync(0xffffffffu, part_, 2); \
  if(q==0){ float yv_ = fmaf((cu), Dv, part_) * siluf(cz); \
    __nv_bfloat16 hh_,ll_; split_bf16(yv_,hh_,ll_); \
    size_t i_ = ((size_t)s*LL + (lidx))*DI + d; \
    pk[i_]=hh_; pk[(size_t)M4*DI + i_]=ll_; } }while(0)

__global__ void scan_gate_pack_kernel(const float* __restrict__ xc, const float* __restrict__ delta,
                                      const float* __restrict__ xd_all, const float* __restrict__ A_log,
                                      const float* __restrict__ Dp, const float* __restrict__ xz,
                                      __nv_bfloat16* __restrict__ pk){
  int t = blockIdx.x*blockDim.x + threadIdx.x;
  if(t >= SS*DI*4) return;
  const int q = t & 3;
  const int ch = t >> 2;
  const int d = ch % DI, s = ch / DI;
  float Ar[4];
  #pragma unroll
  for(int j=0;j<4;j++) Ar[j] = -__expf(A_log[d*NS + 4*q + j]);
  float a1 = -__expf(A_log[d*NS]);
  bool okl = true;
  #pragma unroll
  for(int j=0;j<4;j++){
    float expect = (4*q+j+1)*a1;
    okl = okl && (fabsf(Ar[j]-expect) <= 1e-5f*fabsf(expect));
  }
  unsigned bal = __ballot_sync(0xffffffffu, okl);
  int qb = (threadIdx.x & 31) & ~3;
  bool fast = (((bal >> qb) & 0xFu) == 0xFu);
  float Dv = Dp[d];
  float h0=0.f,h1=0.f,h2=0.f,h3=0.f;
  const float* up = xc    + (size_t)s*LL*DI + d;
  const float* dp = delta + (size_t)s*LL*DI + d;
  const float* xd = xd_all + (size_t)s*LL*XDP;
  const int sb = (s<2)? s : (s-2);
  const float* zp = xz + (size_t)sb*LL*2*DI + DI + d;
  const bool mir = (s>=2);

  float d0[2],u0[2],z0[2],d1[2],u1[2],z1[2];
  float4 B0[2],C0[2],B1[2],C1[2];
  z0[0]=z0[1]=0.f; z1[0]=z1[1]=0.f;
  SCN_LOADP(0, d0,u0,B0,C0,z0);
  for(int base=0; base<LL; base+=4){
    SCN_LOADP(base+2, d1,u1,B1,C1,z1);
    SCN_STEP(base+0, d0[0],u0[0],B0[0],C0[0],z0[0]);
    SCN_STEP(base+1, d0[1],u0[1],B0[1],C0[1],z0[1]);
    SCN_LOADP(base+4, d0,u0,B0,C0,z0);
    SCN_STEP(base+2, d1[0],u1[0],B1[0],C1[0],z1[0]);
    SCN_STEP(base+3, d1[1],u1[1],B1[1],C1[1],z1[1]);
  }
}

// a*silu(gate) -> packed split-bf16 (for fc2 GEMM input)
__global__ void fc_gate_pack_kernel(const float* __restrict__ big, __nv_bfloat16* __restrict__ pk){
  int i=blockIdx.x*blockDim.x+threadIdx.x;
  if(i>=SS*LL*DI) return;
  int r=i/DI, j=i%DI;
  float a = big[(size_t)r*2*DI + j];
  float b = big[(size_t)r*2*DI + DI + j];
  float v = a*siluf(b);
  __nv_bfloat16 hh,ll; split_bf16(v,hh,ll);
  pk[i]=hh; pk[(size_t)M4*DI + i]=ll;
}

__global__ void mean_kernel(const float* __restrict__ fin, float* __restrict__ out){
  int i=blockIdx.x*blockDim.x+threadIdx.x;
  if(i>=BB*DM) return;
  int b=i/DM, j=i%DM;
  float s=0.f;
  for(int l=0;l<LL;l++) s += fin[((size_t)(b*LL+l))*DM+j];
  out[i] = s*(1.f/LL);
}

// ---------------- fused weight pack: ALL weights, BOTH layers, one launch ----------------
#define WPA (2*DI*DM)     // in_proj / fc1 per-layer elems
#define WPB (DM*DI)       // out_proj / fc2 per-layer elems
#define WPC (XDP*DI)      // padded x_proj per-layer elems
#define WP_TOTAL (NLAYER*(2*WPA + 2*WPB + WPC))

__global__ void wpack_all_kernel(const float* __restrict__ in_proj, const float* __restrict__ fc1,
                                 const float* __restrict__ out_proj, const float* __restrict__ fc2,
                                 const float* __restrict__ x_proj,
                                 __nv_bfloat16* __restrict__ pw_in, __nv_bfloat16* __restrict__ pw_fc1,
                                 __nv_bfloat16* __restrict__ pw_out, __nv_bfloat16* __restrict__ pw_fc2,
                                 __nv_bfloat16* __restrict__ pw_xp){
  int i = blockIdx.x*blockDim.x+threadIdx.x;
  if(i >= WP_TOTAL) return;
  float v; __nv_bfloat16* dst; size_t off; size_t plane;
  if(i < NLAYER*WPA){                              // in_proj
    int li = i / WPA, j = i % WPA;
    v = in_proj[(size_t)li*WPA + j];
    dst = pw_in + (size_t)li*2*WPA; off = j; plane = WPA;
  } else if(i < 2*NLAYER*WPA){                     // fc1
    int k = i - NLAYER*WPA;
    int li = k / WPA, j = k % WPA;
    v = fc1[(size_t)li*WPA + j];
    dst = pw_fc1 + (size_t)li*2*WPA; off = j; plane = WPA;
  } else if(i < 2*NLAYER*WPA + NLAYER*WPB){        // out_proj
    int k = i - 2*NLAYER*WPA;
    int li = k / WPB, j = k % WPB;
    v = out_proj[(size_t)li*WPB + j];
    dst = pw_out + (size_t)li*2*WPB; off = j; plane = WPB;
  } else if(i < 2*NLAYER*WPA + 2*NLAYER*WPB){      // fc2
    int k = i - 2*NLAYER*WPA - NLAYER*WPB;
    int li = k / WPB, j = k % WPB;
    v = fc2[(size_t)li*WPB + j];
    dst = pw_fc2 + (size_t)li*2*WPB; off = j; plane = WPB;
  } else {                                         // x_proj (padded)
    int k = i - 2*NLAYER*WPA - 2*NLAYER*WPB;
    int li = k / WPC, j = k % WPC;
    int row = j / DI, col = j % DI;
    v = (row < XD) ? x_proj[(size_t)li*XD*DI + (size_t)row*DI + col] : 0.f;
    dst = pw_xp + (size_t)li*2*WPC; off = j; plane = WPC;
  }
  __nv_bfloat16 hh,ll; split_bf16(v,hh,ll);
  dst[off] = hh; dst[plane + off] = ll;
}

// ---------------- HMMA (mma.sync bf16, split 3-pass) GEMM, BK=16 (proven R13) ----------------
// Supports split-K via gridDim.z: block z computes K-range [z*Klen, (z+1)*Klen)
// and writes its partial to C + z*CzStride.
__device__ __forceinline__ uint32_t smem_u32(const void* p){
  uint32_t a;
  asm("{ .reg .u64 t; cvta.to.shared.u64 t, %1; cvt.u32.u64 %0, t; }" : "=r"(a) : "l"(p));
  return a;
}
#define LDSM4(r, addr) \
  asm volatile("ldmatrix.sync.aligned.m8n8.x4.shared.b16 {%0,%1,%2,%3}, [%4];" \
    : "=r"((r)[0]),"=r"((r)[1]),"=r"((r)[2]),"=r"((r)[3]) : "r"(addr))
#define MMA16(d, a, b0, b1) \
  asm volatile("mma.sync.aligned.m16n8k16.row.col.f32.bf16.bf16.f32 " \
    "{%0,%1,%2,%3}, {%4,%5,%6,%7}, {%8,%9}, {%0,%1,%2,%3};" \
    : "+f"((d)[0]),"+f"((d)[1]),"+f"((d)[2]),"+f"((d)[3]) \
    : "r"((a)[0]),"r"((a)[1]),"r"((a)[2]),"r"((a)[3]), "r"(b0),"r"(b1))
#define CPA16(dst,src) asm volatile("cp.async.cg.shared.global [%0], [%1], 16;" :: "r"(dst), "l"(src))
#define CPCOMMIT() asm volatile("cp.async.commit_group;" ::: "memory")
#define CPWAIT2()  asm volatile("cp.async.wait_group 2;" ::: "memory")

#define HM_STAGES 4
#define HM_PLANE_BYTES 4096
#define HM_STAGE_BYTES 16384
#define HM_SMEM (HM_STAGES*HM_STAGE_BYTES)

__device__ __forceinline__ uint32_t hm_off(int row, int half){
  return (uint32_t)((row>>3)*256 + (row&7)*16 + half*128);
}

__global__ void __launch_bounds__(256,2) mm_hmma(
    int Kfull, int Klen, int N,
    const __nv_bfloat16* __restrict__ Ap,
    const __nv_bfloat16* __restrict__ Bp,
    float* __restrict__ C, size_t CzStride)
{
  extern __shared__ __align__(128) char smem_[];
  const int tid = threadIdx.x, wid = tid>>5, lane = tid&31;
  const int bm = blockIdx.y, bn = blockIdx.x;
  const int koff = blockIdx.z * Klen;
  const size_t aplane = (size_t)gridDim.y*128*Kfull;
  const size_t bplane = (size_t)N*Kfull;
  uint32_t sbase = smem_u32(smem_);
  C += (size_t)blockIdx.z * CzStride;

  const int lrow = tid>>1, lhalf = tid&1;
  const __nv_bfloat16* gA = Ap + (size_t)(bm*128 + lrow)*Kfull + koff + lhalf*8;
  const __nv_bfloat16* gB = Bp + (size_t)(bn*128 + lrow)*Kfull + koff + lhalf*8;
  const uint32_t sdst = sbase + hm_off(lrow, lhalf);

  const int T = Klen>>4;
  const int warp_m = wid>>1, warp_n = wid&1;
  const int lq = lane&15, lh2 = lane>>4;
  uint32_t aoff[2], boff[4];
  #pragma unroll
  for(int mi=0;mi<2;mi++) aoff[mi] = hm_off(warp_m*32+mi*16+lq, lh2);
  #pragma unroll
  for(int j=0;j<4;j++)    boff[j]  = hm_off(warp_n*64+j*16+lq, lh2);

  float acc[2][8][4];
  #pragma unroll
  for(int mi=0;mi<2;mi++)
    #pragma unroll
    for(int f=0;f<8;f++)
      #pragma unroll
      for(int q=0;q<4;q++) acc[mi][f][q]=0.f;

  #pragma unroll
  for(int t=0;t<3;t++){
    uint32_t d = sdst + (uint32_t)t*HM_STAGE_BYTES;
    const __nv_bfloat16* a = gA + t*16;
    const __nv_bfloat16* b = gB + t*16;
    CPA16(d,                     a);
    CPA16(d +   HM_PLANE_BYTES,  a + aplane);
    CPA16(d + 2*HM_PLANE_BYTES,  b);
    CPA16(d + 3*HM_PLANE_BYTES,  b + bplane);
    CPCOMMIT();
  }

  for(int t=0;t<T;t++){
    CPWAIT2();
    __syncthreads();
    uint32_t st_ = sbase + (uint32_t)(t & (HM_STAGES-1))*HM_STAGE_BYTES;
    uint32_t ah[2][4], al[2][4], bb[4][4];
    #pragma unroll
    for(int mi=0;mi<2;mi++){
      LDSM4(ah[mi], st_ + aoff[mi]);
      LDSM4(al[mi], st_ + HM_PLANE_BYTES + aoff[mi]);
    }
    #pragma unroll
    for(int j=0;j<4;j++) LDSM4(bb[j], st_ + 2*HM_PLANE_BYTES + boff[j]);
    #pragma unroll
    for(int mi=0;mi<2;mi++){
      #pragma unroll
      for(int f=0;f<8;f++){
        const int j=f>>1, sel=f&1;
        MMA16(acc[mi][f], ah[mi], bb[j][sel], bb[j][sel+2]);
        MMA16(acc[mi][f], al[mi], bb[j][sel], bb[j][sel+2]);
      }
    }
    #pragma unroll
    for(int j=0;j<4;j++) LDSM4(bb[j], st_ + 3*HM_PLANE_BYTES + boff[j]);
    #pragma unroll
    for(int mi=0;mi<2;mi++){
      #pragma unroll
      for(int f=0;f<8;f++){
        const int j=f>>1, sel=f&1;
        MMA16(acc[mi][f], ah[mi], bb[j][sel], bb[j][sel+2]);
      }
    }
    int tn = t+3;
    if(tn < T){
      uint32_t d = sdst + (uint32_t)(tn & (HM_STAGES-1))*HM_STAGE_BYTES;
      const __nv_bfloat16* a = gA + tn*16;
      const __nv_bfloat16* b = gB + tn*16;
      CPA16(d,                     a);
      CPA16(d +   HM_PLANE_BYTES,  a + aplane);
      CPA16(d + 2*HM_PLANE_BYTES,  b);
      CPA16(d + 3*HM_PLANE_BYTES,  b + bplane);
    }
    CPCOMMIT();
  }

  const int tr = lane>>2, tc = (lane&3)*2;
  const int row0 = bm*128 + warp_m*32;
  const int col0 = bn*128 + warp_n*64;
  #pragma unroll
  for(int mi=0;mi<2;mi++){
    #pragma unroll
    for(int f=0;f<8;f++){
      float* c0 = C + (size_t)(row0+mi*16+tr)*N + col0 + f*8 + tc;
      float2 v0; v0.x=acc[mi][f][0]; v0.y=acc[mi][f][1];
      float2 v1; v1.x=acc[mi][f][2]; v1.y=acc[mi][f][3];
      *(float2*)c0 = v0;
      *(float2*)(c0 + 8*(size_t)N) = v1;
    }
  }
}

// ---------------- fallback FFMA GEMM (delta: K=48) ----------------
template<int BM,int BN,int TM,int TN,int BK>
__global__ void __launch_bounds__(256) gemm_nt(
    int M,int N,int K,int lda,
    const float* __restrict__ A, const float* __restrict__ Bw,
    float* __restrict__ C, const float* __restrict__ bias, int act)
{
  __shared__ float As[BK][BM];
  __shared__ float Bs[BK][BN];
  const int t  = threadIdx.x;
  const int bm = blockIdx.y*BM, bn = blockIdx.x*BN;
  const int TCOL = BN/TN;
  const int tx = t % TCOL, ty = t / TCOL;
  const int KQ = BK/4;
  float acc[TM][TN];
  #pragma unroll
  for(int i=0;i<TM;i++)
    #pragma unroll
    for(int j=0;j<TN;j++) acc[i][j]=0.f;

  for(int k0=0;k0<K;k0+=BK){
    for(int i=t;i<BM*KQ;i+=256){
      int row = i/KQ, kq = (i%KQ)*4;
      float4 v = *(const float4*)(A + (size_t)(bm+row)*lda + k0 + kq);
      As[kq][row]=v.x; As[kq+1][row]=v.y; As[kq+2][row]=v.z; As[kq+3][row]=v.w;
    }
    for(int i=t;i<BN*KQ;i+=256){
      int row = i/KQ, kq = (i%KQ)*4;
      int gn = bn+row;
      float4 v = make_float4(0.f,0.f,0.f,0.f);
      if(gn<N) v = *(const float4*)(Bw + (size_t)gn*K + k0 + kq);
      Bs[kq][row]=v.x; Bs[kq+1][row]=v.y; Bs[kq+2][row]=v.z; Bs[kq+3][row]=v.w;
    }
    __syncthreads();
    #pragma unroll
    for(int kk=0;kk<BK;kk++){
      float a[TM], b[TN];
      #pragma unroll
      for(int i=0;i<TM;i++) a[i]=As[kk][ty*TM+i];
      #pragma unroll
      for(int j=0;j<TN;j++) b[j]=Bs[kk][tx*TN+j];
      #pragma unroll
      for(int i=0;i<TM;i++)
        #pragma unroll
        for(int j=0;j<TN;j++) acc[i][j] = fmaf(a[i],b[j],acc[i][j]);
    }
    __syncthreads();
  }
  #pragma unroll
  for(int i=0;i<TM;i++){
    int gm = bm + ty*TM + i;
    #pragma unroll
    for(int j=0;j<TN;j++){
      int gn = bn + tx*TN + j;
      if(gn<N){
        float c = acc[i][j];
        if(bias) c += bias[gn];
        if(act==1) c = (c>20.f)? c : log1pf(__expf(c));
        C[(size_t)gm*N + gn] = c;
      }
    }
  }
}

// ---------------- launcher ----------------
extern "C" void kernel_launch(void* const* d_in, const int* in_sizes, int n_in,
                              void* d_out, int out_size){
  const int*   ids    = (const int*)  d_in[0];
  const float* emb    = (const float*)d_in[1];
  const float* norm_w = (const float*)d_in[2];
  const float* norm_b = (const float*)d_in[3];
  const float* in_proj= (const float*)d_in[4];
  const float* conv_w = (const float*)d_in[5];
  const float* conv_b = (const float*)d_in[6];
  const float* x_proj = (const float*)d_in[7];
  const float* dt_w   = (const float*)d_in[8];
  const float* dt_b   = (const float*)d_in[9];
  const float* A_log  = (const float*)d_in[10];
  const float* Dw     = (const float*)d_in[11];
  const float* out_proj=(const float*)d_in[12];
  const float* norm2_w= (const float*)d_in[13];
  const float* norm2_b= (const float*)d_in[14];
  const float* fc1    = (const float*)d_in[15];
  const float* fc2    = (const float*)d_in[16];
  const float* normf_w= (const float*)d_in[17];
  const float* normf_b= (const float*)d_in[18];
  float* out = (float*)d_out;

  float *p_h,*p_res,*p_resA,*p_xz,*p_xc,*p_xdbl,*p_delta,*p_bo,*p_bo2,*p_fin;
  __nv_bfloat16 *pa768,*pa1536,*pw_in,*pw_fc1,*pw_out,*pw_fc2,*pw_xp;
  cudaGetSymbolAddress((void**)&p_h,    g_h);
  cudaGetSymbolAddress((void**)&p_res,  g_res);
  cudaGetSymbolAddress((void**)&p_resA, g_resA);
  cudaGetSymbolAddress((void**)&p_xz,   g_xz);
  cudaGetSymbolAddress((void**)&p_xc,   g_xc);
  cudaGetSymbolAddress((void**)&p_xdbl, g_xdbl);
  cudaGetSymbolAddress((void**)&p_delta,g_delta);
  cudaGetSymbolAddress((void**)&p_bo,   g_bo);
  cudaGetSymbolAddress((void**)&p_bo2,  g_bo2);
  cudaGetSymbolAddress((void**)&p_fin,  g_fin);
  cudaGetSymbolAddress((void**)&pa768,  g_pa768);
  cudaGetSymbolAddress((void**)&pa1536, g_pa1536);
  cudaGetSymbolAddress((void**)&pw_in,  g_pw_in);
  cudaGetSymbolAddress((void**)&pw_fc1, g_pw_fc1);
  cudaGetSymbolAddress((void**)&pw_out, g_pw_out);
  cudaGetSymbolAddress((void**)&pw_fc2, g_pw_fc2);
  cudaGetSymbolAddress((void**)&pw_xp,  g_pw_xp);

  cudaFuncSetAttribute(mm_hmma, cudaFuncAttributeMaxDynamicSharedMemorySize, HM_SMEM);

  const int TP=256;
  const size_t boStride = (size_t)M4*DM;
  // Launch order tuned so the ncu-captured launch (my #4) is mm_hmma(in_proj L0).
  wpack_all_kernel<<<(WP_TOTAL+TP-1)/TP,TP>>>(in_proj, fc1, out_proj, fc2, x_proj,
                                              pw_in, pw_fc1, pw_out, pw_fc2, pw_xp);           // 1
  embed_kernel<<<(BB*LL*DM+TP-1)/TP,TP>>>(ids, emb, p_h);                                     // 2
  aug_ln_pack_kernel<<<BB*LL,256>>>(p_h, p_res, p_resA, pa768, norm_w, norm_b, 0);            // 3
  { dim3 g(2*DI/128, M2/128, 1);
    mm_hmma<<<g,256,HM_SMEM>>>(DM, DM, 2*DI, pa768, pw_in, p_xz, 0); }                        // 4 <- profile me

  for(int li=0; li<NLAYER; li++){
    const float* cw = conv_w  + (size_t)li*DI*4;
    const float* cb = conv_b  + (size_t)li*DI;
    const float* dw = dt_w    + (size_t)li*DI*DTR;
    const float* db = dt_b    + (size_t)li*DI;
    const float* al = A_log   + (size_t)li*DI*NS;
    const float* Dl = Dw      + (size_t)li*DI;
    const float* n2w= norm2_w + (size_t)li*DM;
    const float* n2b= norm2_b + (size_t)li*DM;
    const __nv_bfloat16* wF1 = pw_fc1 + (size_t)li*2*(2*DI)*DM;
    const __nv_bfloat16* wOu = pw_out + (size_t)li*2*DM*DI;
    const __nv_bfloat16* wF2 = pw_fc2 + (size_t)li*2*DM*DI;
    const __nv_bfloat16* wXp = pw_xp  + (size_t)li*2*XDP*DI;

    if(li==1){
      aug_ln_pack_kernel<<<BB*LL,256>>>(p_h, p_res, p_resA, pa768,
                                        norm_w + (size_t)1*DM, norm_b + (size_t)1*DM, 1);
      dim3 g(2*DI/128, M2/128, 1);
      mm_hmma<<<g,256,HM_SMEM>>>(DM, DM, 2*DI, pa768, pw_in + (size_t)1*2*(2*DI)*DM, p_xz, 0);
    }

    // conv + silu + split-pack xc (mirror-aware, reads fwd-only xz)
    conv_silu_pack_kernel<<<(SS*LL*DI+TP-1)/TP,TP>>>(p_xz, cw, cb, p_xc, pa1536);

    // x_dbl(padded) = xc @ x_proj_pad^T  (HMMA, N=128)
    { dim3 g(1, M4/128, 1);
      mm_hmma<<<g,256,HM_SMEM>>>(DI, DI, XDP, pa1536, wXp, p_xdbl, 0); }

    // delta = softplus(dt @ dt_w^T + dt_b)  (K=48, lda=XDP)
    { dim3 g(DI/128, M4/128); gemm_nt<128,128,8,8,16><<<g,256>>>(M4, DI, DTR, XDP, p_xdbl, dw, p_delta, db, 1); }

    // selective scan + gate + pack (feeds out_proj)
    scan_gate_pack_kernel<<<(SS*DI*4+127)/128,128>>>(p_xc, p_delta, p_xdbl, al, Dl, p_xz, pa1536);

    // mixer_out = y @ out_proj^T (HMMA, split-K x2: partials in p_bo/p_bo2)
    { dim3 g(DM/128, M4/128, 2);
      mm_hmma<<<g,256,HM_SMEM>>>(DI, DI/2, DM, pa1536, wOu, p_bo, (size_t)(p_bo2 - p_bo)); }

    // res += (bo + bo2) ; x2 = LN(res, norm2) -> packed (feeds fc1 only)
    ln_kernel<<<M4,256>>>(p_bo, p_bo2, p_resA, p_resA, nullptr, pa768, M4*DM, n2w, n2b);

    // fc1 (HMMA)
    { dim3 g(2*DI/128, M4/128, 1);
      mm_hmma<<<g,256,HM_SMEM>>>(DM, DM, 2*DI, pa768, wF1, p_xz, 0); }

    // gated MLP -> packed (feeds fc2 only)
    fc_gate_pack_kernel<<<(SS*LL*DI+TP-1)/TP,TP>>>(p_xz, pa1536);

    // fc2 (HMMA, split-K x2)
    { dim3 g(DM/128, M4/128, 2);
      mm_hmma<<<g,256,HM_SMEM>>>(DI, DI/2, DM, pa1536, wF2, p_bo, (size_t)(p_bo2 - p_bo)); }

    // fused final-norm + combine (sums split-K partials)
    ln_combine_kernel<<<BB*LL,256>>>(p_bo, p_bo2, p_resA, p_h, p_res, normf_w, normf_b);
  }

  ln_kernel<<<BB*LL,256>>>(p_h, nullptr, p_res, nullptr, p_fin, nullptr, 0, normf_w, normf_b);
  mean_kernel<<<(BB*DM+TP-1)/TP,TP>>>(p_fin, out);
}

// round 16
// speedup vs baseline: 1.1418x; 1.0299x over previous
#include <cuda_runtime.h>
#include <cuda_bf16.h>
#include <math.h>
#include <stdint.h>

#define BB 2
#define LL 1024
#define DM 768
#define NLAYER 2
#define DI 1536
#define NS 16
#define DTR 48
#define XD 80           // DTR + 2*NS
#define XDP 128         // padded x_dbl width
#define SS 4            // augmented batch: [fwd b0, fwd b1, bwd b0, bwd b1]
#define M4 (SS*LL)      // 4096 rows (augmented)
#define M2 (2*LL)       // 2048 rows (fwd only, in_proj GEMM)

// ---------------- scratch (static __device__, no allocation) ----------------
__device__ __align__(128) float g_h[BB*LL*DM];
__device__ __align__(128) float g_res[BB*LL*DM];
__device__ __align__(128) float g_resA[SS*LL*DM];
__device__ __align__(128) float g_xz[M2*2*DI];          // fwd only
__device__ __align__(128) float g_xc[SS*LL*DI];
__device__ __align__(128) float g_xdbl[M4*XDP];
__device__ __align__(128) float g_xdblP[4*M4*XDP];      // x_proj split-K partials
__device__ __align__(128) float g_delta[SS*LL*DI];
__device__ __align__(128) float g_boP[3*M4*DM];         // out/fc2 split-K partials (z=3)
__device__ __align__(128) float g_fin[BB*LL*DM];

// split-bf16 activation/weight planes: [hi plane][lo plane], row-major
__device__ __align__(128) __nv_bfloat16 g_pa768 [2*M4*DM];
__device__ __align__(128) __nv_bfloat16 g_pa1536[2*M4*DI];
__device__ __align__(128) __nv_bfloat16 g_pw_in [NLAYER*2*(2*DI)*DM];
__device__ __align__(128) __nv_bfloat16 g_pw_fc1[NLAYER*2*(2*DI)*DM];
__device__ __align__(128) __nv_bfloat16 g_pw_out[NLAYER*2*DM*DI];
__device__ __align__(128) __nv_bfloat16 g_pw_fc2[NLAYER*2*DM*DI];
__device__ __align__(128) __nv_bfloat16 g_pw_xp [NLAYER*2*XDP*DI];

__device__ __forceinline__ float siluf(float x){ return x/(1.f+__expf(-x)); }

__device__ __forceinline__ void split_bf16(float v, __nv_bfloat16& h, __nv_bfloat16& l){
  h = __float2bfloat16(v);
  l = __float2bfloat16(v - __bfloat162float(h));
}

// ---------------- elementwise kernels ----------------
__global__ void embed_kernel(const int* __restrict__ ids, const float* __restrict__ emb,
                             float* __restrict__ out){
  int i = blockIdx.x*blockDim.x+threadIdx.x;
  if(i>=BB*LL*DM) return;
  int d=i%DM; int t=i/DM;
  out[i] = emb[(size_t)ids[t]*DM + d];
}

// Fused: v = h (+res); resA[fwd]=resA[bwd-mirror]=v; LN(v) -> split-bf16 planes (FWD rows only).
__global__ void aug_ln_pack_kernel(const float* __restrict__ h, const float* __restrict__ res,
                                   float* __restrict__ resA, __nv_bfloat16* __restrict__ pk,
                                   const float* __restrict__ w, const float* __restrict__ bias,
                                   int use_res){
  int r = blockIdx.x;              // 0 .. BB*LL-1
  int b = r / LL, l = r % LL;
  size_t fbase = (size_t)(b*LL + l)*DM;
  size_t rbase = (size_t)((2+b)*LL + (LL-1-l))*DM;
  float v[3]; float s=0.f,s2=0.f;
  #pragma unroll
  for(int j=0;j<3;j++){
    int idx = threadIdx.x + j*256;
    float t = h[fbase+idx];
    if(use_res) t += res[fbase+idx];
    v[j]=t; s+=t; s2+=t*t;
    resA[fbase+idx]=t; resA[rbase+idx]=t;
  }
  #pragma unroll
  for(int o=16;o>0;o>>=1){ s+=__shfl_xor_sync(0xffffffffu,s,o); s2+=__shfl_xor_sync(0xffffffffu,s2,o); }
  __shared__ float sh[2][8];
  int wid=threadIdx.x>>5, lane=threadIdx.x&31;
  if(lane==0){ sh[0][wid]=s; sh[1][wid]=s2; }
  __syncthreads();
  if(threadIdx.x<32){
    float a = lane<8? sh[0][lane]:0.f;
    float b2= lane<8? sh[1][lane]:0.f;
    #pragma unroll
    for(int o=4;o>0;o>>=1){ a+=__shfl_xor_sync(0xffffffffu,a,o); b2+=__shfl_xor_sync(0xffffffffu,b2,o); }
    if(lane==0){ sh[0][0]=a; sh[1][0]=b2; }
  }
  __syncthreads();
  float mean = sh[0][0]*(1.f/DM);
  float var  = fmaxf(sh[1][0]*(1.f/DM) - mean*mean, 0.f);
  float inv  = rsqrtf(var + 1e-5f);
  #pragma unroll
  for(int j=0;j<3;j++){
    int idx = threadIdx.x + j*256;
    float o2 = (v[j]-mean)*inv*w[idx] + bias[idx];
    __nv_bfloat16 hh,ll; split_bf16(o2,hh,ll);
    pk[fbase+idx]=hh; pk[(size_t)M2*DM + fbase+idx]=ll;
  }
}

// Row LayerNorm over DM=768. Input = sum of nparts partials (stride pstride),
// optional pre-add, fp32 sum writeback, fp32 out, packed split-bf16 out.
__global__ void ln_kernel(const float* __restrict__ in, size_t pstride, int nparts,
                          const float* __restrict__ addin,
                          float* __restrict__ sumout, float* __restrict__ out,
                          __nv_bfloat16* __restrict__ pk, int planeN,
                          const float* __restrict__ w, const float* __restrict__ bias){
  int r = blockIdx.x;
  size_t base = (size_t)r*DM;
  float v[3]; float s=0.f,s2=0.f;
  #pragma unroll
  for(int j=0;j<3;j++){
    int idx = threadIdx.x + j*256;
    float t = in[base+idx];
    for(int p=1;p<nparts;p++) t += in[base+idx + (size_t)p*pstride];
    if(addin) t += addin[base+idx];
    v[j]=t; s+=t; s2+=t*t;
  }
  if(sumout){
    #pragma unroll
    for(int j=0;j<3;j++) sumout[base+threadIdx.x+j*256]=v[j];
  }
  #pragma unroll
  for(int o=16;o>0;o>>=1){ s+=__shfl_xor_sync(0xffffffffu,s,o); s2+=__shfl_xor_sync(0xffffffffu,s2,o); }
  __shared__ float sh[2][8];
  int wid=threadIdx.x>>5, lane=threadIdx.x&31;
  if(lane==0){ sh[0][wid]=s; sh[1][wid]=s2; }
  __syncthreads();
  if(threadIdx.x<32){
    float a = lane<8? sh[0][lane]:0.f;
    float b2= lane<8? sh[1][lane]:0.f;
    #pragma unroll
    for(int o=4;o>0;o>>=1){ a+=__shfl_xor_sync(0xffffffffu,a,o); b2+=__shfl_xor_sync(0xffffffffu,b2,o); }
    if(lane==0){ sh[0][0]=a; sh[1][0]=b2; }
  }
  __syncthreads();
  float mean = sh[0][0]*(1.f/DM);
  float var  = fmaxf(sh[1][0]*(1.f/DM) - mean*mean, 0.f);
  float inv  = rsqrtf(var + 1e-5f);
  #pragma unroll
  for(int j=0;j<3;j++){
    int idx = threadIdx.x + j*256;
    float o2 = (v[j]-mean)*inv*w[idx] + bias[idx];
    if(out) out[base+idx] = o2;
    if(pk){
      __nv_bfloat16 hh,ll; split_bf16(o2,hh,ll);
      pk[base+idx] = hh; pk[(size_t)planeN + base+idx] = ll;
    }
  }
}

// Fused final-norm + bidirectional combine; bo = sum of 3 split-K partials (stride pst).
__global__ void ln_combine_kernel(const float* __restrict__ bo, size_t pst,
                                  const float* __restrict__ resA,
                                  float* __restrict__ h, float* __restrict__ res,
                                  const float* __restrict__ w, const float* __restrict__ bias){
  int r = blockIdx.x;              // 0..BB*LL-1
  int b = r / LL, l = r % LL;
  size_t f  = (size_t)(b*LL + l)*DM;
  size_t rr = (size_t)((2+b)*LL + (LL-1-l))*DM;
  float vf[3], vr[3];
  float sf=0.f,s2f=0.f,sr=0.f,s2r=0.f;
  #pragma unroll
  for(int j=0;j<3;j++){
    int idx = threadIdx.x + j*256;
    float tf = bo[f+idx]  + bo[f+idx+pst]  + bo[f+idx+2*pst];
    float tr = bo[rr+idx] + bo[rr+idx+pst] + bo[rr+idx+2*pst];
    vf[j]=tf; sf+=tf; s2f+=tf*tf;
    vr[j]=tr; sr+=tr; s2r+=tr*tr;
  }
  #pragma unroll
  for(int o=16;o>0;o>>=1){
    sf+=__shfl_xor_sync(0xffffffffu,sf,o); s2f+=__shfl_xor_sync(0xffffffffu,s2f,o);
    sr+=__shfl_xor_sync(0xffffffffu,sr,o); s2r+=__shfl_xor_sync(0xffffffffu,s2r,o);
  }
  __shared__ float sh[4][8];
  int wid=threadIdx.x>>5, lane=threadIdx.x&31;
  if(lane==0){ sh[0][wid]=sf; sh[1][wid]=s2f; sh[2][wid]=sr; sh[3][wid]=s2r; }
  __syncthreads();
  if(threadIdx.x<32){
    float a0 = lane<8? sh[0][lane]:0.f;
    float a1 = lane<8? sh[1][lane]:0.f;
    float a2 = lane<8? sh[2][lane]:0.f;
    float a3 = lane<8? sh[3][lane]:0.f;
    #pragma unroll
    for(int o=4;o>0;o>>=1){
      a0+=__shfl_xor_sync(0xffffffffu,a0,o); a1+=__shfl_xor_sync(0xffffffffu,a1,o);
      a2+=__shfl_xor_sync(0xffffffffu,a2,o); a3+=__shfl_xor_sync(0xffffffffu,a3,o);
    }
    if(lane==0){ sh[0][0]=a0; sh[1][0]=a1; sh[2][0]=a2; sh[3][0]=a3; }
  }
  __syncthreads();
  float mf = sh[0][0]*(1.f/DM);
  float invf = rsqrtf(fmaxf(sh[1][0]*(1.f/DM)-mf*mf,0.f)+1e-5f);
  float mr = sh[2][0]*(1.f/DM);
  float invr = rsqrtf(fmaxf(sh[3][0]*(1.f/DM)-mr*mr,0.f)+1e-5f);
  #pragma unroll
  for(int j=0;j<3;j++){
    int idx = threadIdx.x + j*256;
    float of = (vf[j]-mf)*invf*w[idx] + bias[idx];
    float orr= (vr[j]-mr)*invr*w[idx] + bias[idx];
    h[f+idx]   = of + orr;
    res[f+idx] = resA[f+idx] + resA[rr+idx];
  }
}

// depthwise causal conv + silu (mirror-aware, fwd-only xz); writes fp32 xc + split-bf16 planes
__global__ void conv_silu_pack_kernel(const float* __restrict__ xz, const float* __restrict__ w,
                                      const float* __restrict__ b, float* __restrict__ xc,
                                      __nv_bfloat16* __restrict__ pk){
  int i = blockIdx.x*blockDim.x+threadIdx.x;
  if(i>=SS*LL*DI) return;
  int d=i%DI; int l=(i/DI)%LL; int s=i/(DI*LL);
  float acc = b[d];
  if(s<2){
    const float* xin = xz + (size_t)s*LL*2*DI + d;
    #pragma unroll
    for(int j=0;j<4;j++){
      int ll=l-3+j;
      if(ll>=0) acc = fmaf(w[d*4+j], xin[(size_t)ll*2*DI], acc);
    }
  } else {
    const float* xin = xz + (size_t)(s-2)*LL*2*DI + d;
    #pragma unroll
    for(int j=0;j<4;j++){
      int ll=l-3+j;
      if(ll>=0) acc = fmaf(w[d*4+j], xin[(size_t)(LL-1-ll)*2*DI], acc);
    }
  }
  float v = siluf(acc);
  xc[i] = v;
  __nv_bfloat16 hh,ll2; split_bf16(v,hh,ll2);
  pk[i]=hh; pk[(size_t)M4*DI + i]=ll2;
}

// sum 4 x_proj split-K partials
__global__ void reduce4_kernel(const float* __restrict__ p, float* __restrict__ o){
  int i = blockIdx.x*blockDim.x+threadIdx.x;
  if(i >= M4*XDP) return;
  o[i] = p[i] + p[i + (size_t)M4*XDP] + p[i + 2*(size_t)M4*XDP] + p[i + 3*(size_t)M4*XDP];
}

// ---------------- selective scan: pair-wise double-buffered prefetch ----------------
#define SCN_LOADP(l0, D, U, Bv, Cv, Z) do{ \
  _Pragma("unroll") \
  for(int j_=0;j_<2;j_++){ \
    int l_ = (l0)+j_; if(l_>LL-1) l_=LL-1; \
    D[j_]=dp[(size_t)l_*DI]; U[j_]=up[(size_t)l_*DI]; \
    const float* nx_ = xd + (size_t)l_*XDP; \
    Bv[j_]=*(const float4*)(nx_+DTR+4*q); \
    Cv[j_]=*(const float4*)(nx_+DTR+NS+4*q); \
    if(q==0){ int zi_ = mir? (LL-1-l_) : l_; Z[j_]=zp[(size_t)zi_*2*DI]; } \
  } }while(0)

#define SCN_STEP(lidx, cdl, cu, cB, cC, cz) do{ \
  float du_ = (cdl)*(cu); float dA0,dA1,dA2,dA3; \
  if(fast){ float e1=__expf((cdl)*a1); float e2=e1*e1,e3=e2*e1,e4=e2*e2; \
    float base_; if(q==0) base_=1.f; else if(q==1) base_=e4; else if(q==2) base_=e4*e4; else base_=e4*e4*e4; \
    dA0=base_*e1; dA1=base_*e2; dA2=base_*e3; dA3=base_*e4; } \
  else { dA0=__expf((cdl)*Ar[0]); dA1=__expf((cdl)*Ar[1]); dA2=__expf((cdl)*Ar[2]); dA3=__expf((cdl)*Ar[3]); } \
  h0=fmaf(dA0,h0,du_*(cB).x); h1=fmaf(dA1,h1,du_*(cB).y); \
  h2=fmaf(dA2,h2,du_*(cB).z); h3=fmaf(dA3,h3,du_*(cB).w); \
  float part_ = fmaf(h0,(cC).x, fmaf(h1,(cC).y, fmaf(h2,(cC).z, h3*(cC).w))); \
  part_ += __shfl_xor_sync(0xffffffffu, part_, 1); \
  part_ += __shfl_xor_sync(0xffffffffu, part_, 2); \
  if(q==0){ float yv_ = fmaf((cu), Dv, part_) * siluf(cz); \
    __nv_bfloat16 hh_,ll_; split_bf16(yv_,hh_,ll_); \
    size_t i_ = ((size_t)s*LL + (lidx))*DI + d; \
    pk[i_]=hh_; pk[(size_t)M4*DI + i_]=ll_; } }while(0)

__global__ void scan_gate_pack_kernel(const float* __restrict__ xc, const float* __restrict__ delta,
                                      const float* __restrict__ xd_all, const float* __restrict__ A_log,
                                      const float* __restrict__ Dp, const float* __restrict__ xz,
                                      __nv_bfloat16* __restrict__ pk){
  int t = blockIdx.x*blockDim.x + threadIdx.x;
  if(t >= SS*DI*4) return;
  const int q = t & 3;
  const int ch = t >> 2;
  const int d = ch % DI, s = ch / DI;
  float Ar[4];
  #pragma unroll
  for(int j=0;j<4;j++) Ar[j] = -__expf(A_log[d*NS + 4*q + j]);
  float a1 = -__expf(A_log[d*NS]);
  bool okl = true;
  #pragma unroll
  for(int j=0;j<4;j++){
    float expect = (4*q+j+1)*a1;
    okl = okl && (fabsf(Ar[j]-expect) <= 1e-5f*fabsf(expect));
  }
  unsigned bal = __ballot_sync(0xffffffffu, okl);
  int qb = (threadIdx.x & 31) & ~3;
  bool fast = (((bal >> qb) & 0xFu) == 0xFu);
  float Dv = Dp[d];
  float h0=0.f,h1=0.f,h2=0.f,h3=0.f;
  const float* up = xc    + (size_t)s*LL*DI + d;
  const float* dp = delta + (size_t)s*LL*DI + d;
  const float* xd = xd_all + (size_t)s*LL*XDP;
  const int sb = (s<2)? s : (s-2);
  const float* zp = xz + (size_t)sb*LL*2*DI + DI + d;
  const bool mir = (s>=2);

  float d0[2],u0[2],z0[2],d1[2],u1[2],z1[2];
  float4 B0[2],C0[2],B1[2],C1[2];
  z0[0]=z0[1]=0.f; z1[0]=z1[1]=0.f;
  SCN_LOADP(0, d0,u0,B0,C0,z0);
  for(int base=0; base<LL; base+=4){
    SCN_LOADP(base+2, d1,u1,B1,C1,z1);
    SCN_STEP(base+0, d0[0],u0[0],B0[0],C0[0],z0[0]);
    SCN_STEP(base+1, d0[1],u0[1],B0[1],C0[1],z0[1]);
    SCN_LOADP(base+4, d0,u0,B0,C0,z0);
    SCN_STEP(base+2, d1[0],u1[0],B1[0],C1[0],z1[0]);
    SCN_STEP(base+3, d1[1],u1[1],B1[1],C1[1],z1[1]);
  }
}

// a*silu(gate) -> packed split-bf16 (for fc2 GEMM input)
__global__ void fc_gate_pack_kernel(const float* __restrict__ big, __nv_bfloat16* __restrict__ pk){
  int i=blockIdx.x*blockDim.x+threadIdx.x;
  if(i>=SS*LL*DI) return;
  int r=i/DI, j=i%DI;
  float a = big[(size_t)r*2*DI + j];
  float b = big[(size_t)r*2*DI + DI + j];
  float v = a*siluf(b);
  __nv_bfloat16 hh,ll; split_bf16(v,hh,ll);
  pk[i]=hh; pk[(size_t)M4*DI + i]=ll;
}

__global__ void mean_kernel(const float* __restrict__ fin, float* __restrict__ out){
  int i=blockIdx.x*blockDim.x+threadIdx.x;
  if(i>=BB*DM) return;
  int b=i/DM, j=i%DM;
  float s=0.f;
  for(int l=0;l<LL;l++) s += fin[((size_t)(b*LL+l))*DM+j];
  out[i] = s*(1.f/LL);
}

// ---------------- fused weight pack: ALL weights, BOTH layers, one launch ----------------
#define WPA (2*DI*DM)
#define WPB (DM*DI)
#define WPC (XDP*DI)
#define WP_TOTAL (NLAYER*(2*WPA + 2*WPB + WPC))

__global__ void wpack_all_kernel(const float* __restrict__ in_proj, const float* __restrict__ fc1,
                                 const float* __restrict__ out_proj, const float* __restrict__ fc2,
                                 const float* __restrict__ x_proj,
                                 __nv_bfloat16* __restrict__ pw_in, __nv_bfloat16* __restrict__ pw_fc1,
                                 __nv_bfloat16* __restrict__ pw_out, __nv_bfloat16* __restrict__ pw_fc2,
                                 __nv_bfloat16* __restrict__ pw_xp){
  int i = blockIdx.x*blockDim.x+threadIdx.x;
  if(i >= WP_TOTAL) return;
  float v; __nv_bfloat16* dst; size_t off; size_t plane;
  if(i < NLAYER*WPA){
    int li = i / WPA, j = i % WPA;
    v = in_proj[(size_t)li*WPA + j];
    dst = pw_in + (size_t)li*2*WPA; off = j; plane = WPA;
  } else if(i < 2*NLAYER*WPA){
    int k = i - NLAYER*WPA;
    int li = k / WPA, j = k % WPA;
    v = fc1[(size_t)li*WPA + j];
    dst = pw_fc1 + (size_t)li*2*WPA; off = j; plane = WPA;
  } else if(i < 2*NLAYER*WPA + NLAYER*WPB){
    int k = i - 2*NLAYER*WPA;
    int li = k / WPB, j = k % WPB;
    v = out_proj[(size_t)li*WPB + j];
    dst = pw_out + (size_t)li*2*WPB; off = j; plane = WPB;
  } else if(i < 2*NLAYER*WPA + 2*NLAYER*WPB){
    int k = i - 2*NLAYER*WPA - NLAYER*WPB;
    int li = k / WPB, j = k % WPB;
    v = fc2[(size_t)li*WPB + j];
    dst = pw_fc2 + (size_t)li*2*WPB; off = j; plane = WPB;
  } else {
    int k = i - 2*NLAYER*WPA - 2*NLAYER*WPB;
    int li = k / WPC, j = k % WPC;
    int row = j / DI, col = j % DI;
    v = (row < XD) ? x_proj[(size_t)li*XD*DI + (size_t)row*DI + col] : 0.f;
    dst = pw_xp + (size_t)li*2*WPC; off = j; plane = WPC;
  }
  __nv_bfloat16 hh,ll; split_bf16(v,hh,ll);
  dst[off] = hh; dst[plane + off] = ll;
}

// ---------------- HMMA (mma.sync bf16, split 3-pass) GEMM, BK=16 ----------------
// split-K via gridDim.z: block z computes K-range [z*Klen,(z+1)*Klen),
// writing its partial to C + z*CzStride.
__device__ __forceinline__ uint32_t smem_u32(const void* p){
  uint32_t a;
  asm("{ .reg .u64 t; cvta.to.shared.u64 t, %1; cvt.u32.u64 %0, t; }" : "=r"(a) : "l"(p));
  return a;
}
#define LDSM4(r, addr) \
  asm volatile("ldmatrix.sync.aligned.m8n8.x4.shared.b16 {%0,%1,%2,%3}, [%4];" \
    : "=r"((r)[0]),"=r"((r)[1]),"=r"((r)[2]),"=r"((r)[3]) : "r"(addr))
#define MMA16(d, a, b0, b1) \
  asm volatile("mma.sync.aligned.m16n8k16.row.col.f32.bf16.bf16.f32 " \
    "{%0,%1,%2,%3}, {%4,%5,%6,%7}, {%8,%9}, {%0,%1,%2,%3};" \
    : "+f"((d)[0]),"+f"((d)[1]),"+f"((d)[2]),"+f"((d)[3]) \
    : "r"((a)[0]),"r"((a)[1]),"r"((a)[2]),"r"((a)[3]), "r"(b0),"r"(b1))
#define CPA16(dst,src) asm volatile("cp.async.cg.shared.global [%0], [%1], 16;" :: "r"(dst), "l"(src))
#define CPCOMMIT() asm volatile("cp.async.commit_group;" ::: "memory")
#define CPWAIT2()  asm volatile("cp.async.wait_group 2;" ::: "memory")

#define HM_STAGES 4
#define HM_PLANE_BYTES 4096
#define HM_STAGE_BYTES 16384
#define HM_SMEM (HM_STAGES*HM_STAGE_BYTES)

__device__ __forceinline__ uint32_t hm_off(int row, int half){
  return (uint32_t)((row>>3)*256 + (row&7)*16 + half*128);
}

__global__ void __launch_bounds__(256,2) mm_hmma(
    int Kfull, int Klen, int N,
    const __nv_bfloat16* __restrict__ Ap,
    const __nv_bfloat16* __restrict__ Bp,
    float* __restrict__ C, size_t CzStride)
{
  extern __shared__ __align__(128) char smem_[];
  const int tid = threadIdx.x, wid = tid>>5, lane = tid&31;
  const int bm = blockIdx.y, bn = blockIdx.x;
  const int koff = blockIdx.z * Klen;
  const size_t aplane = (size_t)gridDim.y*128*Kfull;
  const size_t bplane = (size_t)N*Kfull;
  uint32_t sbase = smem_u32(smem_);
  C += (size_t)blockIdx.z * CzStride;

  const int lrow = tid>>1, lhalf = tid&1;
  const __nv_bfloat16* gA = Ap + (size_t)(bm*128 + lrow)*Kfull + koff + lhalf*8;
  const __nv_bfloat16* gB = Bp + (size_t)(bn*128 + lrow)*Kfull + koff + lhalf*8;
  const uint32_t sdst = sbase + hm_off(lrow, lhalf);

  const int T = Klen>>4;
  const int warp_m = wid>>1, warp_n = wid&1;
  const int lq = lane&15, lh2 = lane>>4;
  uint32_t aoff[2], boff[4];
  #pragma unroll
  for(int mi=0;mi<2;mi++) aoff[mi] = hm_off(warp_m*32+mi*16+lq, lh2);
  #pragma unroll
  for(int j=0;j<4;j++)    boff[j]  = hm_off(warp_n*64+j*16+lq, lh2);

  float acc[2][8][4];
  #pragma unroll
  for(int mi=0;mi<2;mi++)
    #pragma unroll
    for(int f=0;f<8;f++)
      #pragma unroll
      for(int q=0;q<4;q++) acc[mi][f][q]=0.f;

  #pragma unroll
  for(int t=0;t<3;t++){
    uint32_t d = sdst + (uint32_t)t*HM_STAGE_BYTES;
    const __nv_bfloat16* a = gA + t*16;
    const __nv_bfloat16* b = gB + t*16;
    CPA16(d,                     a);
    CPA16(d +   HM_PLANE_BYTES,  a + aplane);
    CPA16(d + 2*HM_PLANE_BYTES,  b);
    CPA16(d + 3*HM_PLANE_BYTES,  b + bplane);
    CPCOMMIT();
  }

  for(int t=0;t<T;t++){
    CPWAIT2();
    __syncthreads();
    uint32_t st_ = sbase + (uint32_t)(t & (HM_STAGES-1))*HM_STAGE_BYTES;
    uint32_t ah[2][4], al[2][4], bb[4][4];
    #pragma unroll
    for(int mi=0;mi<2;mi++){
      LDSM4(ah[mi], st_ + aoff[mi]);
      LDSM4(al[mi], st_ + HM_PLANE_BYTES + aoff[mi]);
    }
    #pragma unroll
    for(int j=0;j<4;j++) LDSM4(bb[j], st_ + 2*HM_PLANE_BYTES + boff[j]);
    #pragma unroll
    for(int mi=0;mi<2;mi++){
      #pragma unroll
      for(int f=0;f<8;f++){
        const int j=f>>1, sel=f&1;
        MMA16(acc[mi][f], ah[mi], bb[j][sel], bb[j][sel+2]);
        MMA16(acc[mi][f], al[mi], bb[j][sel], bb[j][sel+2]);
      }
    }
    #pragma unroll
    for(int j=0;j<4;j++) LDSM4(bb[j], st_ + 3*HM_PLANE_BYTES + boff[j]);
    #pragma unroll
    for(int mi=0;mi<2;mi++){
      #pragma unroll
      for(int f=0;f<8;f++){
        const int j=f>>1, sel=f&1;
        MMA16(acc[mi][f], ah[mi], bb[j][sel], bb[j][sel+2]);
      }
    }
    int tn = t+3;
    if(tn < T){
      uint32_t d = sdst + (uint32_t)(tn & (HM_STAGES-1))*HM_STAGE_BYTES;
      const __nv_bfloat16* a = gA + tn*16;
      const __nv_bfloat16* b = gB + tn*16;
      CPA16(d,                     a);
      CPA16(d +   HM_PLANE_BYTES,  a + aplane);
      CPA16(d + 2*HM_PLANE_BYTES,  b);
      CPA16(d + 3*HM_PLANE_BYTES,  b + bplane);
    }
    CPCOMMIT();
  }

  const int tr = lane>>2, tc = (lane&3)*2;
  const int row0 = bm*128 + warp_m*32;
  const int col0 = bn*128 + warp_n*64;
  #pragma unroll
  for(int mi=0;mi<2;mi++){
    #pragma unroll
    for(int f=0;f<8;f++){
      float* c0 = C + (size_t)(row0+mi*16+tr)*N + col0 + f*8 + tc;
      float2 v0; v0.x=acc[mi][f][0]; v0.y=acc[mi][f][1];
      float2 v1; v1.x=acc[mi][f][2]; v1.y=acc[mi][f][3];
      *(float2*)c0 = v0;
      *(float2*)(c0 + 8*(size_t)N) = v1;
    }
  }
}

// ---------------- fallback FFMA GEMM (delta: K=48) ----------------
template<int BM,int BN,int TM,int TN,int BK>
__global__ void __launch_bounds__(256) gemm_nt(
    int M,int N,int K,int lda,
    const float* __restrict__ A, const float* __restrict__ Bw,
    float* __restrict__ C, const float* __restrict__ bias, int act)
{
  __shared__ float As[BK][BM];
  __shared__ float Bs[BK][BN];
  const int t  = threadIdx.x;
  const int bm = blockIdx.y*BM, bn = blockIdx.x*BN;
  const int TCOL = BN/TN;
  const int tx = t % TCOL, ty = t / TCOL;
  const int KQ = BK/4;
  float acc[TM][TN];
  #pragma unroll
  for(int i=0;i<TM;i++)
    #pragma unroll
    for(int j=0;j<TN;j++) acc[i][j]=0.f;

  for(int k0=0;k0<K;k0+=BK){
    for(int i=t;i<BM*KQ;i+=256){
      int row = i/KQ, kq = (i%KQ)*4;
      float4 v = *(const float4*)(A + (size_t)(bm+row)*lda + k0 + kq);
      As[kq][row]=v.x; As[kq+1][row]=v.y; As[kq+2][row]=v.z; As[kq+3][row]=v.w;
    }
    for(int i=t;i<BN*KQ;i+=256){
      int row = i/KQ, kq = (i%KQ)*4;
      int gn = bn+row;
      float4 v = make_float4(0.f,0.f,0.f,0.f);
      if(gn<N) v = *(const float4*)(Bw + (size_t)gn*K + k0 + kq);
      Bs[kq][row]=v.x; Bs[kq+1][row]=v.y; Bs[kq+2][row]=v.z; Bs[kq+3][row]=v.w;
    }
    __syncthreads();
    #pragma unroll
    for(int kk=0;kk<BK;kk++){
      float a[TM], b[TN];
      #pragma unroll
      for(int i=0;i<TM;i++) a[i]=As[kk][ty*TM+i];
      #pragma unroll
      for(int j=0;j<TN;j++) b[j]=Bs[kk][tx*TN+j];
      #pragma unroll
      for(int i=0;i<TM;i++)
        #pragma unroll
        for(int j=0;j<TN;j++) acc[i][j] = fmaf(a[i],b[j],acc[i][j]);
    }
    __syncthreads();
  }
  #pragma unroll
  for(int i=0;i<TM;i++){
    int gm = bm + ty*TM + i;
    #pragma unroll
    for(int j=0;j<TN;j++){
      int gn = bn + tx*TN + j;
      if(gn<N){
        float c = acc[i][j];
        if(bias) c += bias[gn];
        if(act==1) c = (c>20.f)? c : log1pf(__expf(c));
        C[(size_t)gm*N + gn] = c;
      }
    }
  }
}

// ---------------- launcher ----------------
extern "C" void kernel_launch(void* const* d_in, const int* in_sizes, int n_in,
                              void* d_out, int out_size){
  const int*   ids    = (const int*)  d_in[0];
  const float* emb    = (const float*)d_in[1];
  const float* norm_w = (const float*)d_in[2];
  const float* norm_b = (const float*)d_in[3];
  const float* in_proj= (const float*)d_in[4];
  const float* conv_w = (const float*)d_in[5];
  const float* conv_b = (const float*)d_in[6];
  const float* x_proj = (const float*)d_in[7];
  const float* dt_w   = (const float*)d_in[8];
  const float* dt_b   = (const float*)d_in[9];
  const float* A_log  = (const float*)d_in[10];
  const float* Dw     = (const float*)d_in[11];
  const float* out_proj=(const float*)d_in[12];
  const float* norm2_w= (const float*)d_in[13];
  const float* norm2_b= (const float*)d_in[14];
  const float* fc1    = (const float*)d_in[15];
  const float* fc2    = (const float*)d_in[16];
  const float* normf_w= (const float*)d_in[17];
  const float* normf_b= (const float*)d_in[18];
  float* out = (float*)d_out;

  float *p_h,*p_res,*p_resA,*p_xz,*p_xc,*p_xdbl,*p_xdblP,*p_delta,*p_boP,*p_fin;
  __nv_bfloat16 *pa768,*pa1536,*pw_in,*pw_fc1,*pw_out,*pw_fc2,*pw_xp;
  cudaGetSymbolAddress((void**)&p_h,    g_h);
  cudaGetSymbolAddress((void**)&p_res,  g_res);
  cudaGetSymbolAddress((void**)&p_resA, g_resA);
  cudaGetSymbolAddress((void**)&p_xz,   g_xz);
  cudaGetSymbolAddress((void**)&p_xc,   g_xc);
  cudaGetSymbolAddress((void**)&p_xdbl, g_xdbl);
  cudaGetSymbolAddress((void**)&p_xdblP,g_xdblP);
  cudaGetSymbolAddress((void**)&p_delta,g_delta);
  cudaGetSymbolAddress((void**)&p_boP,  g_boP);
  cudaGetSymbolAddress((void**)&p_fin,  g_fin);
  cudaGetSymbolAddress((void**)&pa768,  g_pa768);
  cudaGetSymbolAddress((void**)&pa1536, g_pa1536);
  cudaGetSymbolAddress((void**)&pw_in,  g_pw_in);
  cudaGetSymbolAddress((void**)&pw_fc1, g_pw_fc1);
  cudaGetSymbolAddress((void**)&pw_out, g_pw_out);
  cudaGetSymbolAddress((void**)&pw_fc2, g_pw_fc2);
  cudaGetSymbolAddress((void**)&pw_xp,  g_pw_xp);

  cudaFuncSetAttribute(mm_hmma, cudaFuncAttributeMaxDynamicSharedMemorySize, HM_SMEM);

  const int TP=256;
  const size_t boStride = (size_t)M4*DM;
  // Launch order tuned so the ncu-captured launch (my #4) is mm_hmma(in_proj L0).
  wpack_all_kernel<<<(WP_TOTAL+TP-1)/TP,TP>>>(in_proj, fc1, out_proj, fc2, x_proj,
                                              pw_in, pw_fc1, pw_out, pw_fc2, pw_xp);           // 1
  embed_kernel<<<(BB*LL*DM+TP-1)/TP,TP>>>(ids, emb, p_h);                                     // 2
  aug_ln_pack_kernel<<<BB*LL,256>>>(p_h, p_res, p_resA, pa768, norm_w, norm_b, 0);            // 3
  { dim3 g(2*DI/128, M2/128, 1);
    mm_hmma<<<g,256,HM_SMEM>>>(DM, DM, 2*DI, pa768, pw_in, p_xz, 0); }                        // 4 <- profile me

  for(int li=0; li<NLAYER; li++){
    const float* cw = conv_w  + (size_t)li*DI*4;
    const float* cb = conv_b  + (size_t)li*DI;
    const float* dw = dt_w    + (size_t)li*DI*DTR;
    const float* db = dt_b    + (size_t)li*DI;
    const float* al = A_log   + (size_t)li*DI*NS;
    const float* Dl = Dw      + (size_t)li*DI;
    const float* n2w= norm2_w + (size_t)li*DM;
    const float* n2b= norm2_b + (size_t)li*DM;
    const __nv_bfloat16* wF1 = pw_fc1 + (size_t)li*2*(2*DI)*DM;
    const __nv_bfloat16* wOu = pw_out + (size_t)li*2*DM*DI;
    const __nv_bfloat16* wF2 = pw_fc2 + (size_t)li*2*DM*DI;
    const __nv_bfloat16* wXp = pw_xp  + (size_t)li*2*XDP*DI;

    if(li==1){
      aug_ln_pack_kernel<<<BB*LL,256>>>(p_h, p_res, p_resA, pa768,
                                        norm_w + (size_t)1*DM, norm_b + (size_t)1*DM, 1);
      dim3 g(2*DI/128, M2/128, 1);
      mm_hmma<<<g,256,HM_SMEM>>>(DM, DM, 2*DI, pa768, pw_in + (size_t)1*2*(2*DI)*DM, p_xz, 0);
    }

    // conv + silu + split-pack xc (mirror-aware, reads fwd-only xz)
    conv_silu_pack_kernel<<<(SS*LL*DI+TP-1)/TP,TP>>>(p_xz, cw, cb, p_xc, pa1536);

    // x_dbl(padded) = xc @ x_proj_pad^T  (HMMA, N=128, split-K x4)
    { dim3 g(1, M4/128, 4);
      mm_hmma<<<g,256,HM_SMEM>>>(DI, DI/4, XDP, pa1536, wXp, p_xdblP, (size_t)M4*XDP); }
    reduce4_kernel<<<(M4*XDP+TP-1)/TP,TP>>>(p_xdblP, p_xdbl);

    // delta = softplus(dt @ dt_w^T + dt_b)  (K=48, lda=XDP)
    { dim3 g(DI/128, M4/128); gemm_nt<128,128,8,8,16><<<g,256>>>(M4, DI, DTR, XDP, p_xdbl, dw, p_delta, db, 1); }

    // selective scan + gate + pack (feeds out_proj)
    scan_gate_pack_kernel<<<(SS*DI*4+127)/128,128>>>(p_xc, p_delta, p_xdbl, al, Dl, p_xz, pa1536);

    // mixer_out = y @ out_proj^T (HMMA, split-K x3: partials in boP)
    { dim3 g(DM/128, M4/128, 3);
      mm_hmma<<<g,256,HM_SMEM>>>(DI, DI/3, DM, pa1536, wOu, p_boP, boStride); }

    // res += sum(boP) ; x2 = LN(res, norm2) -> packed (feeds fc1 only)
    ln_kernel<<<M4,256>>>(p_boP, boStride, 3, p_resA, p_resA, nullptr, pa768, M4*DM, n2w, n2b);

    // fc1 (HMMA)
    { dim3 g(2*DI/128, M4/128, 1);
      mm_hmma<<<g,256,HM_SMEM>>>(DM, DM, 2*DI, pa768, wF1, p_xz, 0); }

    // gated MLP -> packed (feeds fc2 only)
    fc_gate_pack_kernel<<<(SS*LL*DI+TP-1)/TP,TP>>>(p_xz, pa1536);

    // fc2 (HMMA, split-K x3)
    { dim3 g(DM/128, M4/128, 3);
      mm_hmma<<<g,256,HM_SMEM>>>(DI, DI/3, DM, pa1536, wF2, p_boP, boStride); }

    // fused final-norm + combine (sums 3 split-K partials)
    ln_combine_kernel<<<BB*LL,256>>>(p_boP, boStride, p_resA, p_h, p_res, normf_w, normf_b);
  }

  ln_kernel<<<BB*LL,256>>>(p_h, 0, 1, p_res, nullptr, p_fin, nullptr, 0, normf_w, normf_b);
  mean_kernel<<<(BB*DM+TP-1)/TP,TP>>>(p_fin, out);
}